// round 3
// baseline (speedup 1.0000x reference)
#include <cuda_runtime.h>
#include <cstdint>

// ---------------- problem dims (fixed by dataset) ----------------
#define N_MAX   50000
#define E_MAX   800000
#define DIN     768
#define DH      256
#define DOUT    128
#define BATCH   1024

// ---------------- static scratch (no allocations allowed) ----------------
__device__ float g_H1[(size_t)N_MAX * DH];   // relu(x@W1+b1)
__device__ float g_G [(size_t)N_MAX * DH];   // H@Wg (reused for both convs)
__device__ float g_H2[(size_t)N_MAX * DH];   // conv1 output
__device__ float g_O2[(size_t)BATCH * DH];   // conv2 output (only first 1024 rows needed)
__device__ float g_H3[(size_t)BATCH * DOUT]; // relu(O2@W2+b2)
__device__ int   g_deg[N_MAX];
__device__ float g_dinv[N_MAX];
__device__ int   g_rowptr[N_MAX + 1];
__device__ int   g_cursor[N_MAX];
__device__ int   g_col[E_MAX];
__device__ int   g_is64;                      // edge_index dtype flag

// ---------------- small helpers ----------------
__device__ __forceinline__ float4 f4_fma(float s, float4 a, float4 acc) {
    acc.x = fmaf(s, a.x, acc.x); acc.y = fmaf(s, a.y, acc.y);
    acc.z = fmaf(s, a.z, acc.z); acc.w = fmaf(s, a.w, acc.w);
    return acc;
}

// ---------------- dtype sniff ----------------
// If edge_index is little-endian int64 with values < 2^31, every odd int32
// word is 0. If it is int32, odd words are random node ids (~never all 0).
__global__ void sniff_kernel(const int* __restrict__ ei32) {
    int all0 = 1;
    for (int i = 0; i < 64; i++)
        if (ei32[2 * i + 1] != 0) { all0 = 0; break; }
    g_is64 = all0;
}

__device__ __forceinline__ int load_idx(const void* ei, size_t pos) {
    if (g_is64) return (int)((const long long*)ei)[pos];
    return ((const int*)ei)[pos];
}

// ---------------- graph preprocessing ----------------
__global__ void hist_kernel(const void* __restrict__ ei, int E, int n) {
    int e = blockIdx.x * blockDim.x + threadIdx.x;
    if (e >= E) return;
    int d = load_idx(ei, (size_t)E + e);   // dst row
    if ((unsigned)d < (unsigned)n) atomicAdd(&g_deg[d], 1);
}

__global__ void dinv_kernel(int n) {
    int v = blockIdx.x * blockDim.x + threadIdx.x;
    if (v >= n) return;
    g_dinv[v] = rsqrtf((float)(g_deg[v] + 1));  // +1 self loop
}

// single-block exclusive scan of g_deg -> g_rowptr / g_cursor
__global__ void scan_kernel(int n) {
    __shared__ int sdata[1024];
    __shared__ int carry;
    int t = threadIdx.x;
    if (t == 0) carry = 0;
    __syncthreads();
    for (int base = 0; base < n; base += 1024) {
        int i = base + t;
        int v = (i < n) ? g_deg[i] : 0;
        sdata[t] = v;
        __syncthreads();
        #pragma unroll
        for (int off = 1; off < 1024; off <<= 1) {
            int tmp = (t >= off) ? sdata[t - off] : 0;
            __syncthreads();
            sdata[t] += tmp;
            __syncthreads();
        }
        int excl = carry + sdata[t] - v;
        if (i < n) { g_rowptr[i] = excl; g_cursor[i] = excl; }
        __syncthreads();
        if (t == 0) carry += sdata[1023];
        __syncthreads();
    }
    if (t == 0) g_rowptr[n] = carry;
}

__global__ void fill_kernel(const void* __restrict__ ei, int E, int n) {
    int e = blockIdx.x * blockDim.x + threadIdx.x;
    if (e >= E) return;
    int s = load_idx(ei, (size_t)e);
    int d = load_idx(ei, (size_t)E + e);
    if ((unsigned)d >= (unsigned)n || (unsigned)s >= (unsigned)n) return;
    int pos = atomicAdd(&g_cursor[d], 1);
    g_col[pos] = s;
}

// ---------------- tiled fp32 GEMM: C = op(A@B + bias) ----------------
// BM=BN=128, BK=8, 256 threads, 8x8 per-thread tile
#define BM 128
#define BN 128
#define BK 8
#define TM 8
#define TN 8

__global__ void __launch_bounds__(256)
sgemm_kernel(const float* __restrict__ A, const float* __restrict__ B,
             const float* __restrict__ bias, float* __restrict__ C,
             int M, int N, int K, int doRelu) {
    __shared__ float As[BK][BM];
    __shared__ float Bs[BK][BN];
    int tid = threadIdx.x;
    int bm = blockIdx.y, bn = blockIdx.x;
    int tx = tid & 15, ty = tid >> 4;

    float acc[TM][TN];
    #pragma unroll
    for (int i = 0; i < TM; i++)
        #pragma unroll
        for (int j = 0; j < TN; j++) acc[i][j] = 0.f;

    int rowA = tid >> 1;             // 0..127
    int colA = (tid & 1) * 4;        // 0 or 4
    int rowB = tid >> 5;             // 0..7
    int colB = (tid & 31) * 4;       // 0..124

    int gRowA = bm * BM + rowA;
    bool aValid = gRowA < M;
    const float* Aptr = A + (size_t)(aValid ? gRowA : 0) * K + colA;
    const float* Bptr = B + (size_t)rowB * N + bn * BN + colB;

    for (int k0 = 0; k0 < K; k0 += BK) {
        float4 a4 = aValid ? *(const float4*)Aptr : make_float4(0.f, 0.f, 0.f, 0.f);
        float4 b4 = *(const float4*)Bptr;
        As[colA + 0][rowA] = a4.x;
        As[colA + 1][rowA] = a4.y;
        As[colA + 2][rowA] = a4.z;
        As[colA + 3][rowA] = a4.w;
        *(float4*)&Bs[rowB][colB] = b4;
        __syncthreads();
        #pragma unroll
        for (int k = 0; k < BK; k++) {
            float ra[TM], rb[TN];
            #pragma unroll
            for (int i = 0; i < TM; i += 4) *(float4*)&ra[i] = *(const float4*)&As[k][ty * TM + i];
            #pragma unroll
            for (int j = 0; j < TN; j += 4) *(float4*)&rb[j] = *(const float4*)&Bs[k][tx * TN + j];
            #pragma unroll
            for (int i = 0; i < TM; i++)
                #pragma unroll
                for (int j = 0; j < TN; j++)
                    acc[i][j] = fmaf(ra[i], rb[j], acc[i][j]);
        }
        __syncthreads();
        Aptr += BK;
        Bptr += (size_t)BK * N;
    }

    int crow0 = bm * BM + ty * TM;
    int ccol0 = bn * BN + tx * TN;
    float bvals[TN];
    #pragma unroll
    for (int j = 0; j < TN; j++) bvals[j] = bias ? bias[ccol0 + j] : 0.f;

    #pragma unroll
    for (int i = 0; i < TM; i++) {
        int r = crow0 + i;
        if (r >= M) break;
        float* cptr = C + (size_t)r * N + ccol0;
        #pragma unroll
        for (int j = 0; j < TN; j += 4) {
            float4 v;
            v.x = acc[i][j + 0] + bvals[j + 0];
            v.y = acc[i][j + 1] + bvals[j + 1];
            v.z = acc[i][j + 2] + bvals[j + 2];
            v.w = acc[i][j + 3] + bvals[j + 3];
            if (doRelu) {
                v.x = fmaxf(v.x, 0.f); v.y = fmaxf(v.y, 0.f);
                v.z = fmaxf(v.z, 0.f); v.w = fmaxf(v.w, 0.f);
            }
            *(float4*)(cptr + j) = v;
        }
    }
}

// ---------------- GCN aggregation (gather form, warp per dst row) ----------------
// Out[v] = dinv[v] * ( sum_{u->v} G[u]*dinv[u]  +  G[v]*dinv[v] ) + bias
__global__ void __launch_bounds__(256)
gcn_agg_kernel(const float* __restrict__ G, const float* __restrict__ bias,
               float* __restrict__ Out, int rows) {
    int warp = (blockIdx.x * blockDim.x + threadIdx.x) >> 5;
    int lane = threadIdx.x & 31;
    if (warp >= rows) return;
    int v = warp;
    float dv = g_dinv[v];

    const float4* Gv = (const float4*)(G + (size_t)v * DH);
    float4 acc0 = f4_fma(dv, Gv[lane],      make_float4(0.f, 0.f, 0.f, 0.f));
    float4 acc1 = f4_fma(dv, Gv[lane + 32], make_float4(0.f, 0.f, 0.f, 0.f));

    int s = g_rowptr[v], e = g_rowptr[v + 1];
    for (int i = s; i < e; i++) {
        int u = g_col[i];
        float w = g_dinv[u];
        const float4* Gu = (const float4*)(G + (size_t)u * DH);
        acc0 = f4_fma(w, Gu[lane],      acc0);
        acc1 = f4_fma(w, Gu[lane + 32], acc1);
    }

    const float4* b4 = (const float4*)bias;
    float4 bb0 = b4[lane], bb1 = b4[lane + 32];
    float4 o0, o1;
    o0.x = fmaf(dv, acc0.x, bb0.x); o0.y = fmaf(dv, acc0.y, bb0.y);
    o0.z = fmaf(dv, acc0.z, bb0.z); o0.w = fmaf(dv, acc0.w, bb0.w);
    o1.x = fmaf(dv, acc1.x, bb1.x); o1.y = fmaf(dv, acc1.y, bb1.y);
    o1.z = fmaf(dv, acc1.z, bb1.z); o1.w = fmaf(dv, acc1.w, bb1.w);

    float4* Ov = (float4*)(Out + (size_t)v * DH);
    Ov[lane] = o0;
    Ov[lane + 32] = o1;
}

// ---------------- tiny classifier: logits = H3 @ Wc + bc ----------------
__global__ void classifier_kernel(const float* __restrict__ H3,
                                  const float* __restrict__ Wc,
                                  const float* __restrict__ bc,
                                  float* __restrict__ out, int rows) {
    int idx = blockIdx.x * blockDim.x + threadIdx.x;
    if (idx >= rows * 2) return;
    int r = idx >> 1, c = idx & 1;
    const float* h = H3 + (size_t)r * DOUT;
    float s = bc[c];
    #pragma unroll 8
    for (int k = 0; k < DOUT; k++) s = fmaf(h[k], Wc[k * 2 + c], s);
    out[idx] = s;
}

// ---------------- launch ----------------
extern "C" void kernel_launch(void* const* d_in, const int* in_sizes, int n_in,
                              void* d_out, int out_size) {
    const float* x    = (const float*)d_in[0];
    const void*  ei   = d_in[1];
    const float* W1   = (const float*)d_in[2];
    const float* b1   = (const float*)d_in[3];
    const float* Wg1  = (const float*)d_in[4];
    const float* bg1  = (const float*)d_in[5];
    const float* Wg2  = (const float*)d_in[6];
    const float* bg2  = (const float*)d_in[7];
    const float* W2   = (const float*)d_in[8];
    const float* b2   = (const float*)d_in[9];
    const float* Wc   = (const float*)d_in[10];
    const float* bc   = (const float*)d_in[11];

    int n = in_sizes[0] / DIN;        // 50000
    int E = in_sizes[1] / 2;          // 800000 (element count / 2 for either dtype)
    int batch = out_size / 2;         // 1024
    if (n > N_MAX) n = N_MAX;
    if (E > E_MAX) E = E_MAX;
    if (batch > BATCH) batch = BATCH;

    float *H1, *G, *H2, *O2, *H3;
    int *deg;
    cudaGetSymbolAddress((void**)&H1,  g_H1);
    cudaGetSymbolAddress((void**)&G,   g_G);
    cudaGetSymbolAddress((void**)&H2,  g_H2);
    cudaGetSymbolAddress((void**)&O2,  g_O2);
    cudaGetSymbolAddress((void**)&H3,  g_H3);
    cudaGetSymbolAddress((void**)&deg, g_deg);

    // ---- graph preprocessing ----
    cudaMemsetAsync(deg, 0, (size_t)n * sizeof(int));
    sniff_kernel<<<1, 1>>>((const int*)ei);
    hist_kernel<<<(E + 255) / 256, 256>>>(ei, E, n);
    dinv_kernel<<<(n + 255) / 256, 256>>>(n);
    scan_kernel<<<1, 1024>>>(n);
    fill_kernel<<<(E + 255) / 256, 256>>>(ei, E, n);

    // ---- H1 = relu(x @ W1 + b1)  [n,768]x[768,256] ----
    {
        dim3 grid(DH / BN, (n + BM - 1) / BM);
        sgemm_kernel<<<grid, 256>>>(x, W1, b1, H1, n, DH, DIN, 1);
    }
    // ---- conv1: G = H1 @ Wg1 ; H2 = agg(G) + bg1 (all rows) ----
    {
        dim3 grid(DH / BN, (n + BM - 1) / BM);
        sgemm_kernel<<<grid, 256>>>(H1, Wg1, nullptr, G, n, DH, DH, 0);
        gcn_agg_kernel<<<(n * 32 + 255) / 256, 256>>>(G, bg1, H2, n);
    }
    // ---- conv2: G = H2 @ Wg2 ; O2 = agg(G) + bg2 (ONLY first `batch` rows) ----
    {
        dim3 grid(DH / BN, (n + BM - 1) / BM);
        sgemm_kernel<<<grid, 256>>>(H2, Wg2, nullptr, G, n, DH, DH, 0);
        gcn_agg_kernel<<<(batch * 32 + 255) / 256, 256>>>(G, bg2, O2, batch);
    }
    // ---- H3 = relu(O2 @ W2 + b2)  [batch,256]x[256,128] ----
    {
        dim3 grid(DOUT / BN, (batch + BM - 1) / BM);
        sgemm_kernel<<<grid, 256>>>(O2, W2, b2, H3, batch, DOUT, DH, 1);
    }
    // ---- logits = H3 @ Wc + bc ----
    classifier_kernel<<<(batch * 2 + 255) / 256, 256>>>(H3, Wc, bc, (float*)d_out, batch);
}

// round 6
// speedup vs baseline: 1.6460x; 1.6460x over previous
#include <cuda_runtime.h>
#include <cuda_bf16.h>
#include <cstdint>

// ---------------- problem dims (fixed by dataset) ----------------
#define N_MAX   50000
#define E_MAX   800000
#define DIN     768
#define DH      256
#define DOUT    128
#define BATCH   1024

// ---------------- static scratch (no allocations allowed) ----------------
__device__ float g_H1[(size_t)N_MAX * DH];
__device__ float g_G [(size_t)N_MAX * DH];
__device__ float g_H2[(size_t)N_MAX * DH];
__device__ float g_O2[(size_t)BATCH * DH];
__device__ float g_H3[(size_t)BATCH * DOUT];
__device__ int   g_deg[N_MAX];
__device__ float g_dinv[N_MAX];
__device__ int   g_rowptr[N_MAX + 1];
__device__ int   g_cursor[N_MAX];
__device__ int   g_col[E_MAX];
__device__ int   g_is64;
__device__ int   g_bsum[64];
__device__ int   g_boff[66];
// bf16-split operand buffers
__device__ __nv_bfloat16 g_xh[(size_t)N_MAX * DIN];
__device__ __nv_bfloat16 g_xl[(size_t)N_MAX * DIN];
__device__ __nv_bfloat16 g_Hh[(size_t)N_MAX * DH];
__device__ __nv_bfloat16 g_Hl[(size_t)N_MAX * DH];
__device__ __nv_bfloat16 g_Wth[(size_t)DH * DIN];   // W^T hi  [256, K<=768] row-major [n][k]
__device__ __nv_bfloat16 g_Wtl[(size_t)DH * DIN];   // W^T lo

// ---------------- small helpers ----------------
__device__ __forceinline__ float4 f4_fma(float s, float4 a, float4 acc) {
    acc.x = fmaf(s, a.x, acc.x); acc.y = fmaf(s, a.y, acc.y);
    acc.z = fmaf(s, a.z, acc.z); acc.w = fmaf(s, a.w, acc.w);
    return acc;
}
__device__ __forceinline__ uint32_t smem_to_u32(const void* p) {
    uint32_t a;
    asm("{ .reg .u64 t; cvta.to.shared.u64 t, %1; cvt.u32.u64 %0, t; }" : "=r"(a) : "l"(p));
    return a;
}
__device__ __forceinline__ void cp_async16(uint32_t dst, const void* src) {
    asm volatile("cp.async.cg.shared.global [%0], [%1], 16;" :: "r"(dst), "l"(src));
}
__device__ __forceinline__ void cp_commit() { asm volatile("cp.async.commit_group;"); }
template <int N>
__device__ __forceinline__ void cp_wait() { asm volatile("cp.async.wait_group %0;" :: "n"(N)); }

__device__ __forceinline__ void ldm_x4(uint32_t* r, uint32_t addr) {
    asm volatile("ldmatrix.sync.aligned.m8n8.x4.shared.b16 {%0,%1,%2,%3}, [%4];"
                 : "=r"(r[0]), "=r"(r[1]), "=r"(r[2]), "=r"(r[3]) : "r"(addr));
}
__device__ __forceinline__ void mma_bf16(float* d, const uint32_t* a, const uint32_t* b) {
    asm volatile(
        "mma.sync.aligned.m16n8k16.row.col.f32.bf16.bf16.f32 "
        "{%0,%1,%2,%3}, {%4,%5,%6,%7}, {%8,%9}, {%0,%1,%2,%3};"
        : "+f"(d[0]), "+f"(d[1]), "+f"(d[2]), "+f"(d[3])
        : "r"(a[0]), "r"(a[1]), "r"(a[2]), "r"(a[3]), "r"(b[0]), "r"(b[1]));
}

// ---------------- dtype sniff ----------------
__global__ void sniff_kernel(const int* __restrict__ ei32) {
    int all0 = 1;
    for (int i = 0; i < 64; i++)
        if (ei32[2 * i + 1] != 0) { all0 = 0; break; }
    g_is64 = all0;
}
__device__ __forceinline__ int load_idx(const void* ei, size_t pos) {
    if (g_is64) return (int)((const long long*)ei)[pos];
    return ((const int*)ei)[pos];
}

// ---------------- graph preprocessing ----------------
__global__ void hist_kernel(const void* __restrict__ ei, int E, int n) {
    int e = blockIdx.x * blockDim.x + threadIdx.x;
    if (e >= E) return;
    int d = load_idx(ei, (size_t)E + e);
    if ((unsigned)d < (unsigned)n) atomicAdd(&g_deg[d], 1);
}
__global__ void dinv_kernel(int n) {
    int v = blockIdx.x * blockDim.x + threadIdx.x;
    if (v >= n) return;
    g_dinv[v] = rsqrtf((float)(g_deg[v] + 1));
}
__global__ void scan_part_kernel(int n) {
    __shared__ int wsum[32];
    int t = threadIdx.x, b = blockIdx.x, i = b * 1024 + t;
    int lane = t & 31, w = t >> 5;
    int v = (i < n) ? g_deg[i] : 0;
    int x = v;
    #pragma unroll
    for (int o = 1; o < 32; o <<= 1) { int y = __shfl_up_sync(0xffffffffu, x, o); if (lane >= o) x += y; }
    if (lane == 31) wsum[w] = x;
    __syncthreads();
    if (w == 0) {
        int s = wsum[lane];
        #pragma unroll
        for (int o = 1; o < 32; o <<= 1) { int y = __shfl_up_sync(0xffffffffu, s, o); if (lane >= o) s += y; }
        wsum[lane] = s;
    }
    __syncthreads();
    int off = w ? wsum[w - 1] : 0;
    int incl = x + off;
    if (i < n) g_rowptr[i] = incl - v;
    if (t == 1023) g_bsum[b] = incl;
}
__global__ void scan_top_kernel(int nb) {
    if (threadIdx.x == 0) {
        int acc = 0;
        for (int b = 0; b < nb; b++) { int s = g_bsum[b]; g_boff[b] = acc; acc += s; }
        g_boff[nb] = acc;
    }
}
__global__ void scan_add_kernel(int n, int nb) {
    int i = blockIdx.x * blockDim.x + threadIdx.x;
    if (i < n) {
        int val = g_rowptr[i] + g_boff[i >> 10];
        g_rowptr[i] = val; g_cursor[i] = val;
    }
    if (i == 0) g_rowptr[n] = g_boff[nb];
}
__global__ void fill_kernel(const void* __restrict__ ei, int E, int n) {
    int e = blockIdx.x * blockDim.x + threadIdx.x;
    if (e >= E) return;
    int s = load_idx(ei, (size_t)e);
    int d = load_idx(ei, (size_t)E + e);
    if ((unsigned)d >= (unsigned)n || (unsigned)s >= (unsigned)n) return;
    int pos = atomicAdd(&g_cursor[d], 1);
    g_col[pos] = s;
}

// ---------------- fp32 -> bf16 hi/lo split ----------------
__global__ void split_kernel(const float* __restrict__ A,
                             __nv_bfloat16* __restrict__ hi,
                             __nv_bfloat16* __restrict__ lo, size_t cnt) {
    size_t i = ((size_t)blockIdx.x * blockDim.x + threadIdx.x) * 4;
    if (i + 3 < cnt) {
        float4 a = *(const float4*)(A + i);
        __nv_bfloat16 h0 = __float2bfloat16(a.x), h1 = __float2bfloat16(a.y);
        __nv_bfloat16 h2 = __float2bfloat16(a.z), h3 = __float2bfloat16(a.w);
        __nv_bfloat16 l0 = __float2bfloat16(a.x - __bfloat162float(h0));
        __nv_bfloat16 l1 = __float2bfloat16(a.y - __bfloat162float(h1));
        __nv_bfloat16 l2 = __float2bfloat16(a.z - __bfloat162float(h2));
        __nv_bfloat16 l3 = __float2bfloat16(a.w - __bfloat162float(h3));
        *(__nv_bfloat162*)(hi + i)     = __nv_bfloat162(h0, h1);
        *(__nv_bfloat162*)(hi + i + 2) = __nv_bfloat162(h2, h3);
        *(__nv_bfloat162*)(lo + i)     = __nv_bfloat162(l0, l1);
        *(__nv_bfloat162*)(lo + i + 2) = __nv_bfloat162(l2, l3);
    } else {
        for (; i < cnt; i++) {
            float a = A[i];
            __nv_bfloat16 h = __float2bfloat16(a);
            hi[i] = h; lo[i] = __float2bfloat16(a - __bfloat162float(h));
        }
    }
}
// W [K,256] fp32 -> W^T [256,K] bf16 hi/lo
__global__ void wtr_kernel(const float* __restrict__ W,
                           __nv_bfloat16* __restrict__ hi,
                           __nv_bfloat16* __restrict__ lo, int K) {
    int idx = blockIdx.x * blockDim.x + threadIdx.x;
    if (idx >= K * 256) return;
    int k = idx >> 8, nn = idx & 255;
    float a = W[idx];
    __nv_bfloat16 h = __float2bfloat16(a);
    size_t o = (size_t)nn * K + k;
    hi[o] = h; lo[o] = __float2bfloat16(a - __bfloat162float(h));
}

// ---------------- mma.sync bf16-split GEMM ----------------
// C[M,256] = (Ah+Al) @ (Bh+Bl)^T (+bias)(+relu), B* = W^T [256,K] row-major [n][k]
// CTA 256 thr = 8 warps (4M x 2N), tile 128x128, BK=32, double-buffered cp.async.
#define ROW_B   80                      // padded row stride bytes (40 bf16)
#define TILE_B  (128 * ROW_B)           // 10240 bytes per operand tile
#define STAGE_B (4 * TILE_B)            // Ah|Al|Bh|Bl
#define TC_SMEM (2 * STAGE_B)           // 81920

__global__ void __launch_bounds__(256)
tc_gemm_kernel(const __nv_bfloat16* __restrict__ Ah, const __nv_bfloat16* __restrict__ Al,
               const __nv_bfloat16* __restrict__ Bh, const __nv_bfloat16* __restrict__ Bl,
               const float* __restrict__ bias, float* __restrict__ C,
               int M, int K, int doRelu) {
    extern __shared__ char smem[];
    const uint32_t sbase = smem_to_u32(smem);
    const int tid = threadIdx.x, lane = tid & 31, wid = tid >> 5;
    const int bm = blockIdx.x, bn = blockIdx.y;
    const int warpM = wid >> 1, warpN = wid & 1;

    // global source rows for the loader
    const int lrow = tid >> 1, lseg = tid & 1;      // 2 threads per tile row, 32B each
    int arow = bm * 128 + lrow; if (arow >= M) arow = M - 1;
    const __nv_bfloat16* aH = Ah + (size_t)arow * K + lseg * 16;
    const __nv_bfloat16* aL = Al + (size_t)arow * K + lseg * 16;
    const __nv_bfloat16* bH = Bh + (size_t)(bn * 128 + lrow) * K + lseg * 16;
    const __nv_bfloat16* bL = Bl + (size_t)(bn * 128 + lrow) * K + lseg * 16;
    const uint32_t sdst = sbase + (uint32_t)lrow * ROW_B + (uint32_t)lseg * 32;

    const int nk = K >> 5;

    auto issue_stage = [&](int c) {
        const uint32_t so = (uint32_t)(c & 1) * STAGE_B;
        const int k0 = c << 5;
        cp_async16(sdst + so,                 aH + k0);
        cp_async16(sdst + so + 16,            aH + k0 + 8);
        cp_async16(sdst + so + TILE_B,        aL + k0);
        cp_async16(sdst + so + TILE_B + 16,   aL + k0 + 8);
        cp_async16(sdst + so + 2 * TILE_B,      bH + k0);
        cp_async16(sdst + so + 2 * TILE_B + 16, bH + k0 + 8);
        cp_async16(sdst + so + 3 * TILE_B,      bL + k0);
        cp_async16(sdst + so + 3 * TILE_B + 16, bL + k0 + 8);
        cp_commit();
    };

    float acc[2][8][4];
    #pragma unroll
    for (int mi = 0; mi < 2; mi++)
        #pragma unroll
        for (int ni = 0; ni < 8; ni++)
            #pragma unroll
            for (int r = 0; r < 4; r++) acc[mi][ni][r] = 0.f;

    issue_stage(0);

    // ldmatrix lane addressing (constant across chunks except k-step/stage offset)
    const uint32_t a_off = (uint32_t)(warpM * 32 + (lane & 15)) * ROW_B + ((lane >> 4) << 4);
    // B x4 loads a pair of n-tiles: lanes 0-15 -> ni0, 16-31 -> ni0+1; (lane>>3)&1 -> k half
    const uint32_t b_off = (uint32_t)(warpN * 64 + ((lane >> 4) << 3) + (lane & 7)) * ROW_B
                         + (((lane >> 3) & 1) << 4);

    for (int c = 0; c < nk; c++) {
        if (c + 1 < nk) { issue_stage(c + 1); cp_wait<1>(); }
        else            { cp_wait<0>(); }
        __syncthreads();

        const uint32_t so = sbase + (uint32_t)(c & 1) * STAGE_B;
        #pragma unroll
        for (int ks = 0; ks < 2; ks++) {
            uint32_t a_h[2][4], a_l[2][4];
            #pragma unroll
            for (int mi = 0; mi < 2; mi++) {
                uint32_t off = a_off + (uint32_t)mi * 16 * ROW_B + ks * 32;
                ldm_x4(a_h[mi], so + off);
                ldm_x4(a_l[mi], so + TILE_B + off);
            }
            uint32_t b_h[8][2], b_l[8][2];
            #pragma unroll
            for (int np = 0; np < 4; np++) {
                uint32_t off = b_off + (uint32_t)np * 16 * ROW_B + ks * 32;
                uint32_t t[4];
                ldm_x4(t, so + 2 * TILE_B + off);
                b_h[np * 2][0] = t[0]; b_h[np * 2][1] = t[1];
                b_h[np * 2 + 1][0] = t[2]; b_h[np * 2 + 1][1] = t[3];
                ldm_x4(t, so + 3 * TILE_B + off);
                b_l[np * 2][0] = t[0]; b_l[np * 2][1] = t[1];
                b_l[np * 2 + 1][0] = t[2]; b_l[np * 2 + 1][1] = t[3];
            }
            #pragma unroll
            for (int mi = 0; mi < 2; mi++)
                #pragma unroll
                for (int ni = 0; ni < 8; ni++) {
                    mma_bf16(acc[mi][ni], a_h[mi], b_h[ni]);
                    mma_bf16(acc[mi][ni], a_h[mi], b_l[ni]);
                    mma_bf16(acc[mi][ni], a_l[mi], b_h[ni]);
                }
        }
        __syncthreads();
    }

    // epilogue: thread t in mma tile -> rows (t/4, t/4+8), cols 2*(t%4)+{0,1}
    const int r0 = bm * 128 + warpM * 32 + (lane >> 2);
    const int c0 = bn * 128 + warpN * 64 + (lane & 3) * 2;
    #pragma unroll
    for (int mi = 0; mi < 2; mi++) {
        #pragma unroll
        for (int ni = 0; ni < 8; ni++) {
            int col = c0 + ni * 8;
            float bx = bias ? bias[col] : 0.f;
            float by = bias ? bias[col + 1] : 0.f;
            #pragma unroll
            for (int half = 0; half < 2; half++) {
                int row = r0 + mi * 16 + half * 8;
                if (row < M) {
                    float vx = acc[mi][ni][half * 2 + 0] + bx;
                    float vy = acc[mi][ni][half * 2 + 1] + by;
                    if (doRelu) { vx = fmaxf(vx, 0.f); vy = fmaxf(vy, 0.f); }
                    *(float2*)(C + (size_t)row * 256 + col) = make_float2(vx, vy);
                }
            }
        }
    }
}

// ---------------- fp32 tiled GEMM (tiny 1024-row linear) ----------------
#define BM 128
#define BN 128
#define BK 8
#define TM 8
#define TN 8
__global__ void __launch_bounds__(256)
sgemm_kernel(const float* __restrict__ A, const float* __restrict__ B,
             const float* __restrict__ bias, float* __restrict__ C,
             int M, int N, int K, int doRelu) {
    __shared__ float As[BK][BM];
    __shared__ float Bs[BK][BN];
    int tid = threadIdx.x;
    int bm = blockIdx.y, bn = blockIdx.x;
    int tx = tid & 15, ty = tid >> 4;
    float acc[TM][TN];
    #pragma unroll
    for (int i = 0; i < TM; i++)
        #pragma unroll
        for (int j = 0; j < TN; j++) acc[i][j] = 0.f;
    int rowA = tid >> 1, colA = (tid & 1) * 4;
    int rowB = tid >> 5, colB = (tid & 31) * 4;
    int gRowA = bm * BM + rowA;
    bool aValid = gRowA < M;
    const float* Aptr = A + (size_t)(aValid ? gRowA : 0) * K + colA;
    const float* Bptr = B + (size_t)rowB * N + bn * BN + colB;
    for (int k0 = 0; k0 < K; k0 += BK) {
        float4 a4 = aValid ? *(const float4*)Aptr : make_float4(0.f, 0.f, 0.f, 0.f);
        float4 b4 = *(const float4*)Bptr;
        As[colA + 0][rowA] = a4.x; As[colA + 1][rowA] = a4.y;
        As[colA + 2][rowA] = a4.z; As[colA + 3][rowA] = a4.w;
        *(float4*)&Bs[rowB][colB] = b4;
        __syncthreads();
        #pragma unroll
        for (int k = 0; k < BK; k++) {
            float ra[TM], rb[TN];
            #pragma unroll
            for (int i = 0; i < TM; i += 4) *(float4*)&ra[i] = *(const float4*)&As[k][ty * TM + i];
            #pragma unroll
            for (int j = 0; j < TN; j += 4) *(float4*)&rb[j] = *(const float4*)&Bs[k][tx * TN + j];
            #pragma unroll
            for (int i = 0; i < TM; i++)
                #pragma unroll
                for (int j = 0; j < TN; j++)
                    acc[i][j] = fmaf(ra[i], rb[j], acc[i][j]);
        }
        __syncthreads();
        Aptr += BK; Bptr += (size_t)BK * N;
    }
    int crow0 = bm * BM + ty * TM, ccol0 = bn * BN + tx * TN;
    float bvals[TN];
    #pragma unroll
    for (int j = 0; j < TN; j++) bvals[j] = bias ? bias[ccol0 + j] : 0.f;
    #pragma unroll
    for (int i = 0; i < TM; i++) {
        int r = crow0 + i;
        if (r >= M) break;
        float* cptr = C + (size_t)r * N + ccol0;
        #pragma unroll
        for (int j = 0; j < TN; j += 4) {
            float4 v;
            v.x = acc[i][j + 0] + bvals[j + 0]; v.y = acc[i][j + 1] + bvals[j + 1];
            v.z = acc[i][j + 2] + bvals[j + 2]; v.w = acc[i][j + 3] + bvals[j + 3];
            if (doRelu) {
                v.x = fmaxf(v.x, 0.f); v.y = fmaxf(v.y, 0.f);
                v.z = fmaxf(v.z, 0.f); v.w = fmaxf(v.w, 0.f);
            }
            *(float4*)(cptr + j) = v;
        }
    }
}

// ---------------- GCN aggregation (gather, warp per dst row) ----------------
__global__ void __launch_bounds__(256)
gcn_agg_kernel(const float* __restrict__ G, const float* __restrict__ bias,
               float* __restrict__ Out, int rows) {
    int warp = (blockIdx.x * blockDim.x + threadIdx.x) >> 5;
    int lane = threadIdx.x & 31;
    if (warp >= rows) return;
    int v = warp;
    float dv = g_dinv[v];
    const float4* Gv = (const float4*)(G + (size_t)v * DH);
    float4 acc0 = f4_fma(dv, Gv[lane],      make_float4(0.f, 0.f, 0.f, 0.f));
    float4 acc1 = f4_fma(dv, Gv[lane + 32], make_float4(0.f, 0.f, 0.f, 0.f));
    int s = g_rowptr[v], e = g_rowptr[v + 1];
    for (int i = s; i < e; i++) {
        int u = g_col[i];
        float w = g_dinv[u];
        const float4* Gu = (const float4*)(G + (size_t)u * DH);
        acc0 = f4_fma(w, Gu[lane],      acc0);
        acc1 = f4_fma(w, Gu[lane + 32], acc1);
    }
    const float4* b4 = (const float4*)bias;
    float4 bb0 = b4[lane], bb1 = b4[lane + 32];
    float4 o0, o1;
    o0.x = fmaf(dv, acc0.x, bb0.x); o0.y = fmaf(dv, acc0.y, bb0.y);
    o0.z = fmaf(dv, acc0.z, bb0.z); o0.w = fmaf(dv, acc0.w, bb0.w);
    o1.x = fmaf(dv, acc1.x, bb1.x); o1.y = fmaf(dv, acc1.y, bb1.y);
    o1.z = fmaf(dv, acc1.z, bb1.z); o1.w = fmaf(dv, acc1.w, bb1.w);
    float4* Ov = (float4*)(Out + (size_t)v * DH);
    Ov[lane] = o0; Ov[lane + 32] = o1;
}

// ---------------- tiny classifier ----------------
__global__ void classifier_kernel(const float* __restrict__ H3,
                                  const float* __restrict__ Wc,
                                  const float* __restrict__ bc,
                                  float* __restrict__ out, int rows) {
    int idx = blockIdx.x * blockDim.x + threadIdx.x;
    if (idx >= rows * 2) return;
    int r = idx >> 1, c = idx & 1;
    const float* h = H3 + (size_t)r * DOUT;
    float s = bc[c];
    #pragma unroll 8
    for (int k = 0; k < DOUT; k++) s = fmaf(h[k], Wc[k * 2 + c], s);
    out[idx] = s;
}

// ---------------- launch ----------------
extern "C" void kernel_launch(void* const* d_in, const int* in_sizes, int n_in,
                              void* d_out, int out_size) {
    const float* x    = (const float*)d_in[0];
    const void*  ei   = d_in[1];
    const float* W1   = (const float*)d_in[2];
    const float* b1   = (const float*)d_in[3];
    const float* Wg1  = (const float*)d_in[4];
    const float* bg1  = (const float*)d_in[5];
    const float* Wg2  = (const float*)d_in[6];
    const float* bg2  = (const float*)d_in[7];
    const float* W2   = (const float*)d_in[8];
    const float* b2   = (const float*)d_in[9];
    const float* Wc   = (const float*)d_in[10];
    const float* bc   = (const float*)d_in[11];

    int n = in_sizes[0] / DIN;
    int E = in_sizes[1] / 2;
    int batch = out_size / 2;
    if (n > N_MAX) n = N_MAX;
    if (E > E_MAX) E = E_MAX;
    if (batch > BATCH) batch = BATCH;

    float *H1, *G, *H2, *O2, *H3;
    int *deg;
    __nv_bfloat16 *xh, *xl, *Hh, *Hl, *Wth, *Wtl;
    cudaGetSymbolAddress((void**)&H1,  g_H1);
    cudaGetSymbolAddress((void**)&G,   g_G);
    cudaGetSymbolAddress((void**)&H2,  g_H2);
    cudaGetSymbolAddress((void**)&O2,  g_O2);
    cudaGetSymbolAddress((void**)&H3,  g_H3);
    cudaGetSymbolAddress((void**)&deg, g_deg);
    cudaGetSymbolAddress((void**)&xh,  g_xh);
    cudaGetSymbolAddress((void**)&xl,  g_xl);
    cudaGetSymbolAddress((void**)&Hh,  g_Hh);
    cudaGetSymbolAddress((void**)&Hl,  g_Hl);
    cudaGetSymbolAddress((void**)&Wth, g_Wth);
    cudaGetSymbolAddress((void**)&Wtl, g_Wtl);

    static int smem_set = 0;
    if (!smem_set) {
        cudaFuncSetAttribute(tc_gemm_kernel,
                             cudaFuncAttributeMaxDynamicSharedMemorySize, TC_SMEM);
        smem_set = 1;
    }

    int nb = (n + 1023) / 1024;
    int mtiles = (n + 127) / 128;
    dim3 tcgrid(mtiles, 2);   // 2 col tiles of 128 cover N=256

    // ---- graph preprocessing ----
    cudaMemsetAsync(deg, 0, (size_t)n * sizeof(int));
    sniff_kernel<<<1, 1>>>((const int*)ei);
    hist_kernel<<<(E + 255) / 256, 256>>>(ei, E, n);
    dinv_kernel<<<(n + 255) / 256, 256>>>(n);
    scan_part_kernel<<<nb, 1024>>>(n);
    scan_top_kernel<<<1, 32>>>(nb);
    scan_add_kernel<<<(n + 255) / 256, 256>>>(n, nb);
    fill_kernel<<<(E + 255) / 256, 256>>>(ei, E, n);

    // ---- H1 = relu(x @ W1 + b1) via mma.sync ----
    {
        size_t cnt = (size_t)n * DIN;
        split_kernel<<<(int)((cnt / 4 + 255) / 256), 256>>>(x, xh, xl, cnt);
        wtr_kernel<<<(DIN * 256 + 255) / 256, 256>>>(W1, Wth, Wtl, DIN);
        tc_gemm_kernel<<<tcgrid, 256, TC_SMEM>>>(xh, xl, Wth, Wtl, b1, H1, n, DIN, 1);
    }
    // ---- conv1: G = H1 @ Wg1 ; H2 = agg(G) + bg1 ----
    {
        size_t cnt = (size_t)n * DH;
        split_kernel<<<(int)((cnt / 4 + 255) / 256), 256>>>(H1, Hh, Hl, cnt);
        wtr_kernel<<<(DH * 256 + 255) / 256, 256>>>(Wg1, Wth, Wtl, DH);
        tc_gemm_kernel<<<tcgrid, 256, TC_SMEM>>>(Hh, Hl, Wth, Wtl, nullptr, G, n, DH, 0);
        gcn_agg_kernel<<<(n * 32 + 255) / 256, 256>>>(G, bg1, H2, n);
    }
    // ---- conv2: G = H2 @ Wg2 ; O2 = agg(G) + bg2 (first batch rows) ----
    {
        size_t cnt = (size_t)n * DH;
        split_kernel<<<(int)((cnt / 4 + 255) / 256), 256>>>(H2, Hh, Hl, cnt);
        wtr_kernel<<<(DH * 256 + 255) / 256, 256>>>(Wg2, Wth, Wtl, DH);
        tc_gemm_kernel<<<tcgrid, 256, TC_SMEM>>>(Hh, Hl, Wth, Wtl, nullptr, G, n, DH, 0);
        gcn_agg_kernel<<<(batch * 32 + 255) / 256, 256>>>(G, bg2, O2, batch);
    }
    // ---- H3 = relu(O2 @ W2 + b2) ----
    {
        dim3 grid(DOUT / BN, (batch + BM - 1) / BM);
        sgemm_kernel<<<grid, 256>>>(O2, W2, b2, H3, batch, DOUT, DH, 1);
    }
    classifier_kernel<<<(batch * 2 + 255) / 256, 256>>>(H3, Wc, bc, (float*)d_out, batch);
}

// round 11
// speedup vs baseline: 2.1322x; 1.2953x over previous
#include <cuda_runtime.h>
#include <cuda_bf16.h>
#include <cstdint>

// ---------------- problem dims (fixed by dataset) ----------------
#define N_MAX   50000
#define E_MAX   800000
#define DIN     768
#define DH      256
#define DOUT    128
#define BATCH   1024

// ---------------- static scratch (no allocations allowed) ----------------
__device__ float g_G [(size_t)N_MAX * DH];   // GEMM2 out (full) / GEMM3 out (compact)
__device__ float g_O2[(size_t)BATCH * DH];
__device__ float g_H3[(size_t)BATCH * DOUT];
__device__ int   g_deg[N_MAX];
__device__ float g_dinv[N_MAX];
__device__ int   g_rowptr[N_MAX + 1];
__device__ int   g_cursor[N_MAX];
__device__ int   g_col[E_MAX];
__device__ int   g_is64;
__device__ int   g_bsum[64];
__device__ int   g_boff[66];
// pruning / compaction
__device__ int   g_need[N_MAX];
__device__ int   g_remap[N_MAX];
__device__ int   g_list2[N_MAX];
__device__ int   g_m2;
__device__ int   g_bsum2[64];
__device__ int   g_boff2[66];
// bf16-split operand buffers
__device__ __nv_bfloat16 g_xh[(size_t)N_MAX * DIN];
__device__ __nv_bfloat16 g_xl[(size_t)N_MAX * DIN];
__device__ __nv_bfloat16 g_H1h[(size_t)N_MAX * DH];
__device__ __nv_bfloat16 g_H1l[(size_t)N_MAX * DH];
__device__ __nv_bfloat16 g_H2h[(size_t)N_MAX * DH];   // compact rows
__device__ __nv_bfloat16 g_H2l[(size_t)N_MAX * DH];
__device__ __nv_bfloat16 g_Wth[(size_t)DH * DIN];     // W^T hi [256, K] row-major [n][k]
__device__ __nv_bfloat16 g_Wtl[(size_t)DH * DIN];

// ---------------- small helpers ----------------
__device__ __forceinline__ float4 f4_fma(float s, float4 a, float4 acc) {
    acc.x = fmaf(s, a.x, acc.x); acc.y = fmaf(s, a.y, acc.y);
    acc.z = fmaf(s, a.z, acc.z); acc.w = fmaf(s, a.w, acc.w);
    return acc;
}
__device__ __forceinline__ uint32_t smem_to_u32(const void* p) {
    uint32_t a;
    asm("{ .reg .u64 t; cvta.to.shared.u64 t, %1; cvt.u32.u64 %0, t; }" : "=r"(a) : "l"(p));
    return a;
}
__device__ __forceinline__ void cp_async16(uint32_t dst, const void* src) {
    asm volatile("cp.async.cg.shared.global [%0], [%1], 16;" :: "r"(dst), "l"(src));
}
__device__ __forceinline__ void cp_commit() { asm volatile("cp.async.commit_group;"); }
template <int N>
__device__ __forceinline__ void cp_wait() { asm volatile("cp.async.wait_group %0;" :: "n"(N)); }

__device__ __forceinline__ void ldm_x4(uint32_t* r, uint32_t addr) {
    asm volatile("ldmatrix.sync.aligned.m8n8.x4.shared.b16 {%0,%1,%2,%3}, [%4];"
                 : "=r"(r[0]), "=r"(r[1]), "=r"(r[2]), "=r"(r[3]) : "r"(addr));
}
__device__ __forceinline__ void mma_bf16(float* d, const uint32_t* a, const uint32_t* b) {
    asm volatile(
        "mma.sync.aligned.m16n8k16.row.col.f32.bf16.bf16.f32 "
        "{%0,%1,%2,%3}, {%4,%5,%6,%7}, {%8,%9}, {%0,%1,%2,%3};"
        : "+f"(d[0]), "+f"(d[1]), "+f"(d[2]), "+f"(d[3])
        : "r"(a[0]), "r"(a[1]), "r"(a[2]), "r"(a[3]), "r"(b[0]), "r"(b[1]));
}
__device__ __forceinline__ void split1(float a, __nv_bfloat16& h, __nv_bfloat16& l) {
    h = __float2bfloat16(a);
    l = __float2bfloat16(a - __bfloat162float(h));
}

// ---------------- dtype sniff ----------------
__global__ void sniff_kernel(const int* __restrict__ ei32) {
    int all0 = 1;
    for (int i = 0; i < 64; i++)
        if (ei32[2 * i + 1] != 0) { all0 = 0; break; }
    g_is64 = all0;
}
__device__ __forceinline__ int load_idx(const void* ei, size_t pos) {
    if (g_is64) return (int)((const long long*)ei)[pos];
    return ((const int*)ei)[pos];
}

// ---------------- graph preprocessing ----------------
__global__ void hist_kernel(const void* __restrict__ ei, int E, int n) {
    int e = blockIdx.x * blockDim.x + threadIdx.x;
    if (e >= E) return;
    int d = load_idx(ei, (size_t)E + e);
    if ((unsigned)d < (unsigned)n) atomicAdd(&g_deg[d], 1);
}
__global__ void dinv_kernel(int n) {
    int v = blockIdx.x * blockDim.x + threadIdx.x;
    if (v >= n) return;
    g_dinv[v] = rsqrtf((float)(g_deg[v] + 1));
}
__global__ void scan_part_kernel(int n) {
    __shared__ int wsum[32];
    int t = threadIdx.x, b = blockIdx.x, i = b * 1024 + t;
    int lane = t & 31, w = t >> 5;
    int v = (i < n) ? g_deg[i] : 0;
    int x = v;
    #pragma unroll
    for (int o = 1; o < 32; o <<= 1) { int y = __shfl_up_sync(0xffffffffu, x, o); if (lane >= o) x += y; }
    if (lane == 31) wsum[w] = x;
    __syncthreads();
    if (w == 0) {
        int s = wsum[lane];
        #pragma unroll
        for (int o = 1; o < 32; o <<= 1) { int y = __shfl_up_sync(0xffffffffu, s, o); if (lane >= o) s += y; }
        wsum[lane] = s;
    }
    __syncthreads();
    int off = w ? wsum[w - 1] : 0;
    int incl = x + off;
    if (i < n) g_rowptr[i] = incl - v;
    if (t == 1023) g_bsum[b] = incl;
}
__global__ void scan_top_kernel(int nb) {
    if (threadIdx.x == 0) {
        int acc = 0;
        for (int b = 0; b < nb; b++) { int s = g_bsum[b]; g_boff[b] = acc; acc += s; }
        g_boff[nb] = acc;
    }
}
__global__ void scan_add_kernel(int n, int nb) {
    int i = blockIdx.x * blockDim.x + threadIdx.x;
    if (i < n) {
        int val = g_rowptr[i] + g_boff[i >> 10];
        g_rowptr[i] = val; g_cursor[i] = val;
    }
    if (i == 0) g_rowptr[n] = g_boff[nb];
}
__global__ void fill_kernel(const void* __restrict__ ei, int E, int n) {
    int e = blockIdx.x * blockDim.x + threadIdx.x;
    if (e >= E) return;
    int s = load_idx(ei, (size_t)e);
    int d = load_idx(ei, (size_t)E + e);
    if ((unsigned)d >= (unsigned)n || (unsigned)s >= (unsigned)n) return;
    int pos = atomicAdd(&g_cursor[d], 1);
    g_col[pos] = s;
}

// ---------------- needed-set (rows feeding the final batch) ----------------
__global__ void mark_kernel(const void* __restrict__ ei, int E, int n, int batch) {
    int e = blockIdx.x * blockDim.x + threadIdx.x;
    if (e < batch && e < n) g_need[e] = 1;      // self rows
    if (e >= E) return;
    int d = load_idx(ei, (size_t)E + e);
    if ((unsigned)d < (unsigned)batch) {
        int s = load_idx(ei, (size_t)e);
        if ((unsigned)s < (unsigned)n) g_need[s] = 1;
    }
}
__global__ void cscan_part_kernel(int n) {
    __shared__ int wsum[32];
    int t = threadIdx.x, b = blockIdx.x, i = b * 1024 + t;
    int lane = t & 31, w = t >> 5;
    int v = (i < n) ? g_need[i] : 0;
    int x = v;
    #pragma unroll
    for (int o = 1; o < 32; o <<= 1) { int y = __shfl_up_sync(0xffffffffu, x, o); if (lane >= o) x += y; }
    if (lane == 31) wsum[w] = x;
    __syncthreads();
    if (w == 0) {
        int s = wsum[lane];
        #pragma unroll
        for (int o = 1; o < 32; o <<= 1) { int y = __shfl_up_sync(0xffffffffu, s, o); if (lane >= o) s += y; }
        wsum[lane] = s;
    }
    __syncthreads();
    int off = w ? wsum[w - 1] : 0;
    int incl = x + off;
    if (i < n) g_remap[i] = incl - v;
    if (t == 1023) g_bsum2[b] = incl;
}
__global__ void cscan_top_kernel(int nb) {
    if (threadIdx.x == 0) {
        int acc = 0;
        for (int b = 0; b < nb; b++) { int s = g_bsum2[b]; g_boff2[b] = acc; acc += s; }
        g_boff2[nb] = acc;
    }
}
__global__ void cscan_add_kernel(int n, int nb) {
    int i = blockIdx.x * blockDim.x + threadIdx.x;
    if (i < n) {
        int r = g_remap[i] + g_boff2[i >> 10];
        g_remap[i] = r;
        if (g_need[i]) g_list2[r] = i;
    }
    if (i == 0) g_m2 = g_boff2[nb];
}

// ---------------- fp32 -> bf16 hi/lo split (input x only) ----------------
__global__ void split_kernel(const float* __restrict__ A,
                             __nv_bfloat16* __restrict__ hi,
                             __nv_bfloat16* __restrict__ lo, size_t cnt) {
    size_t i = ((size_t)blockIdx.x * blockDim.x + threadIdx.x) * 4;
    if (i + 3 < cnt) {
        float4 a = *(const float4*)(A + i);
        __nv_bfloat16 h0, h1, h2, h3, l0, l1, l2, l3;
        split1(a.x, h0, l0); split1(a.y, h1, l1);
        split1(a.z, h2, l2); split1(a.w, h3, l3);
        *(__nv_bfloat162*)(hi + i)     = __nv_bfloat162(h0, h1);
        *(__nv_bfloat162*)(hi + i + 2) = __nv_bfloat162(h2, h3);
        *(__nv_bfloat162*)(lo + i)     = __nv_bfloat162(l0, l1);
        *(__nv_bfloat162*)(lo + i + 2) = __nv_bfloat162(l2, l3);
    } else {
        for (; i < cnt; i++) { __nv_bfloat16 h, l; split1(A[i], h, l); hi[i] = h; lo[i] = l; }
    }
}
// W [K,256] fp32 -> W^T [256,K] bf16 hi/lo
__global__ void wtr_kernel(const float* __restrict__ W,
                           __nv_bfloat16* __restrict__ hi,
                           __nv_bfloat16* __restrict__ lo, int K) {
    int idx = blockIdx.x * blockDim.x + threadIdx.x;
    if (idx >= K * 256) return;
    int k = idx >> 8, nn = idx & 255;
    __nv_bfloat16 h, l; split1(W[idx], h, l);
    size_t o = (size_t)nn * K + k;
    hi[o] = h; lo[o] = l;
}

// ---------------- mma.sync bf16-split GEMM ----------------
// C[M,256] = (Ah+Al) @ (Bh+Bl)^T (+bias)(+relu)
// Output: fp32 C, or bf16 hi/lo (Ch/Cl) when C==nullptr.
// Mdev (optional) overrides M with a device-side count (compact GEMM3).
#define ROW_B   80
#define TILE_B  (128 * ROW_B)
#define STAGE_B (4 * TILE_B)
#define TC_SMEM (2 * STAGE_B)

__global__ void __launch_bounds__(256)
tc_gemm_kernel(const __nv_bfloat16* __restrict__ Ah, const __nv_bfloat16* __restrict__ Al,
               const __nv_bfloat16* __restrict__ Bh, const __nv_bfloat16* __restrict__ Bl,
               const float* __restrict__ bias,
               float* __restrict__ C,
               __nv_bfloat16* __restrict__ Ch, __nv_bfloat16* __restrict__ Cl,
               int M, const int* __restrict__ Mdev, int K, int doRelu) {
    if (Mdev) M = *Mdev;
    const int bm = blockIdx.x, bn = blockIdx.y;
    if (bm * 128 >= M) return;

    extern __shared__ char smem[];
    const uint32_t sbase = smem_to_u32(smem);
    const int tid = threadIdx.x, lane = tid & 31, wid = tid >> 5;
    const int warpM = wid >> 1, warpN = wid & 1;

    const int lrow = tid >> 1, lseg = tid & 1;
    int arow = bm * 128 + lrow; if (arow >= M) arow = M - 1;
    const __nv_bfloat16* aH = Ah + (size_t)arow * K + lseg * 16;
    const __nv_bfloat16* aL = Al + (size_t)arow * K + lseg * 16;
    const __nv_bfloat16* bH = Bh + (size_t)(bn * 128 + lrow) * K + lseg * 16;
    const __nv_bfloat16* bL = Bl + (size_t)(bn * 128 + lrow) * K + lseg * 16;
    const uint32_t sdst = sbase + (uint32_t)lrow * ROW_B + (uint32_t)lseg * 32;

    const int nk = K >> 5;

    auto issue_stage = [&](int c) {
        const uint32_t so = (uint32_t)(c & 1) * STAGE_B;
        const int k0 = c << 5;
        cp_async16(sdst + so,                 aH + k0);
        cp_async16(sdst + so + 16,            aH + k0 + 8);
        cp_async16(sdst + so + TILE_B,        aL + k0);
        cp_async16(sdst + so + TILE_B + 16,   aL + k0 + 8);
        cp_async16(sdst + so + 2 * TILE_B,      bH + k0);
        cp_async16(sdst + so + 2 * TILE_B + 16, bH + k0 + 8);
        cp_async16(sdst + so + 3 * TILE_B,      bL + k0);
        cp_async16(sdst + so + 3 * TILE_B + 16, bL + k0 + 8);
        cp_commit();
    };

    float acc[2][8][4];
    #pragma unroll
    for (int mi = 0; mi < 2; mi++)
        #pragma unroll
        for (int ni = 0; ni < 8; ni++)
            #pragma unroll
            for (int r = 0; r < 4; r++) acc[mi][ni][r] = 0.f;

    issue_stage(0);

    const uint32_t a_off = (uint32_t)(warpM * 32 + (lane & 15)) * ROW_B + ((lane >> 4) << 4);
    const uint32_t b_off = (uint32_t)(warpN * 64 + ((lane >> 4) << 3) + (lane & 7)) * ROW_B
                         + (((lane >> 3) & 1) << 4);

    for (int c = 0; c < nk; c++) {
        if (c + 1 < nk) { issue_stage(c + 1); cp_wait<1>(); }
        else            { cp_wait<0>(); }
        __syncthreads();

        const uint32_t so = sbase + (uint32_t)(c & 1) * STAGE_B;
        #pragma unroll
        for (int ks = 0; ks < 2; ks++) {
            uint32_t a_h[2][4], a_l[2][4];
            #pragma unroll
            for (int mi = 0; mi < 2; mi++) {
                uint32_t off = a_off + (uint32_t)mi * 16 * ROW_B + ks * 32;
                ldm_x4(a_h[mi], so + off);
                ldm_x4(a_l[mi], so + TILE_B + off);
            }
            uint32_t b_h[8][2], b_l[8][2];
            #pragma unroll
            for (int np = 0; np < 4; np++) {
                uint32_t off = b_off + (uint32_t)np * 16 * ROW_B + ks * 32;
                uint32_t t[4];
                ldm_x4(t, so + 2 * TILE_B + off);
                b_h[np * 2][0] = t[0]; b_h[np * 2][1] = t[1];
                b_h[np * 2 + 1][0] = t[2]; b_h[np * 2 + 1][1] = t[3];
                ldm_x4(t, so + 3 * TILE_B + off);
                b_l[np * 2][0] = t[0]; b_l[np * 2][1] = t[1];
                b_l[np * 2 + 1][0] = t[2]; b_l[np * 2 + 1][1] = t[3];
            }
            #pragma unroll
            for (int mi = 0; mi < 2; mi++)
                #pragma unroll
                for (int ni = 0; ni < 8; ni++) {
                    mma_bf16(acc[mi][ni], a_h[mi], b_h[ni]);
                    mma_bf16(acc[mi][ni], a_h[mi], b_l[ni]);
                    mma_bf16(acc[mi][ni], a_l[mi], b_h[ni]);
                }
        }
        __syncthreads();
    }

    const int r0 = bm * 128 + warpM * 32 + (lane >> 2);
    const int c0 = bn * 128 + warpN * 64 + (lane & 3) * 2;
    #pragma unroll
    for (int mi = 0; mi < 2; mi++) {
        #pragma unroll
        for (int ni = 0; ni < 8; ni++) {
            int col = c0 + ni * 8;
            float bx = bias ? bias[col] : 0.f;
            float by = bias ? bias[col + 1] : 0.f;
            #pragma unroll
            for (int half = 0; half < 2; half++) {
                int row = r0 + mi * 16 + half * 8;
                if (row < M) {
                    float vx = acc[mi][ni][half * 2 + 0] + bx;
                    float vy = acc[mi][ni][half * 2 + 1] + by;
                    if (doRelu) { vx = fmaxf(vx, 0.f); vy = fmaxf(vy, 0.f); }
                    if (C) {
                        *(float2*)(C + (size_t)row * 256 + col) = make_float2(vx, vy);
                    } else {
                        __nv_bfloat16 hx, lx, hy, ly;
                        split1(vx, hx, lx); split1(vy, hy, ly);
                        *(__nv_bfloat162*)(Ch + (size_t)row * 256 + col) = __nv_bfloat162(hx, hy);
                        *(__nv_bfloat162*)(Cl + (size_t)row * 256 + col) = __nv_bfloat162(lx, ly);
                    }
                }
            }
        }
    }
}

// ---------------- fp32 tiled GEMM (tiny 1024-row linear) ----------------
#define BM 128
#define BN 128
#define BK 8
#define TM 8
#define TN 8
__global__ void __launch_bounds__(256)
sgemm_kernel(const float* __restrict__ A, const float* __restrict__ B,
             const float* __restrict__ bias, float* __restrict__ C,
             int M, int N, int K, int doRelu) {
    __shared__ float As[BK][BM];
    __shared__ float Bs[BK][BN];
    int tid = threadIdx.x;
    int bm = blockIdx.y, bn = blockIdx.x;
    int tx = tid & 15, ty = tid >> 4;
    float acc[TM][TN];
    #pragma unroll
    for (int i = 0; i < TM; i++)
        #pragma unroll
        for (int j = 0; j < TN; j++) acc[i][j] = 0.f;
    int rowA = tid >> 1, colA = (tid & 1) * 4;
    int rowB = tid >> 5, colB = (tid & 31) * 4;
    int gRowA = bm * BM + rowA;
    bool aValid = gRowA < M;
    const float* Aptr = A + (size_t)(aValid ? gRowA : 0) * K + colA;
    const float* Bptr = B + (size_t)rowB * N + bn * BN + colB;
    for (int k0 = 0; k0 < K; k0 += BK) {
        float4 a4 = aValid ? *(const float4*)Aptr : make_float4(0.f, 0.f, 0.f, 0.f);
        float4 b4 = *(const float4*)Bptr;
        As[colA + 0][rowA] = a4.x; As[colA + 1][rowA] = a4.y;
        As[colA + 2][rowA] = a4.z; As[colA + 3][rowA] = a4.w;
        *(float4*)&Bs[rowB][colB] = b4;
        __syncthreads();
        #pragma unroll
        for (int k = 0; k < BK; k++) {
            float ra[TM], rb[TN];
            #pragma unroll
            for (int i = 0; i < TM; i += 4) *(float4*)&ra[i] = *(const float4*)&As[k][ty * TM + i];
            #pragma unroll
            for (int j = 0; j < TN; j += 4) *(float4*)&rb[j] = *(const float4*)&Bs[k][tx * TN + j];
            #pragma unroll
            for (int i = 0; i < TM; i++)
                #pragma unroll
                for (int j = 0; j < TN; j++)
                    acc[i][j] = fmaf(ra[i], rb[j], acc[i][j]);
        }
        __syncthreads();
        Aptr += BK; Bptr += (size_t)BK * N;
    }
    int crow0 = bm * BM + ty * TM, ccol0 = bn * BN + tx * TN;
    float bvals[TN];
    #pragma unroll
    for (int j = 0; j < TN; j++) bvals[j] = bias ? bias[ccol0 + j] : 0.f;
    #pragma unroll
    for (int i = 0; i < TM; i++) {
        int r = crow0 + i;
        if (r >= M) break;
        float* cptr = C + (size_t)r * N + ccol0;
        #pragma unroll
        for (int j = 0; j < TN; j += 4) {
            float4 v;
            v.x = acc[i][j + 0] + bvals[j + 0]; v.y = acc[i][j + 1] + bvals[j + 1];
            v.z = acc[i][j + 2] + bvals[j + 2]; v.w = acc[i][j + 3] + bvals[j + 3];
            if (doRelu) {
                v.x = fmaxf(v.x, 0.f); v.y = fmaxf(v.y, 0.f);
                v.z = fmaxf(v.z, 0.f); v.w = fmaxf(v.w, 0.f);
            }
            *(float4*)(cptr + j) = v;
        }
    }
}

// ---------------- conv1 aggregation over compact list, bf16 hi/lo output ----------------
__global__ void __launch_bounds__(256)
gcn_agg_bf16_kernel(const float* __restrict__ G, const float* __restrict__ bias,
                    __nv_bfloat16* __restrict__ Hh, __nv_bfloat16* __restrict__ Hl) {
    int i = (blockIdx.x * blockDim.x + threadIdx.x) >> 5;
    int lane = threadIdx.x & 31;
    if (i >= g_m2) return;
    int v = g_list2[i];
    float dv = g_dinv[v];

    const float4* Gv = (const float4*)(G + (size_t)v * DH);
    float4 acc0 = f4_fma(dv, Gv[lane],      make_float4(0.f, 0.f, 0.f, 0.f));
    float4 acc1 = f4_fma(dv, Gv[lane + 32], make_float4(0.f, 0.f, 0.f, 0.f));
    int s = g_rowptr[v], e = g_rowptr[v + 1];
    for (int j = s; j < e; j++) {
        int u = g_col[j];
        float w = g_dinv[u];
        const float4* Gu = (const float4*)(G + (size_t)u * DH);
        acc0 = f4_fma(w, Gu[lane],      acc0);
        acc1 = f4_fma(w, Gu[lane + 32], acc1);
    }
    const float4* b4 = (const float4*)bias;
    float4 bb0 = b4[lane], bb1 = b4[lane + 32];
    float o[8];
    o[0] = fmaf(dv, acc0.x, bb0.x); o[1] = fmaf(dv, acc0.y, bb0.y);
    o[2] = fmaf(dv, acc0.z, bb0.z); o[3] = fmaf(dv, acc0.w, bb0.w);
    o[4] = fmaf(dv, acc1.x, bb1.x); o[5] = fmaf(dv, acc1.y, bb1.y);
    o[6] = fmaf(dv, acc1.z, bb1.z); o[7] = fmaf(dv, acc1.w, bb1.w);

    size_t base = (size_t)i * DH;
    #pragma unroll
    for (int p = 0; p < 4; p += 2) {
        __nv_bfloat16 h0, l0, h1, l1;
        split1(o[p], h0, l0); split1(o[p + 1], h1, l1);
        *(__nv_bfloat162*)(Hh + base + lane * 4 + p) = __nv_bfloat162(h0, h1);
        *(__nv_bfloat162*)(Hl + base + lane * 4 + p) = __nv_bfloat162(l0, l1);
    }
    #pragma unroll
    for (int p = 0; p < 4; p += 2) {
        __nv_bfloat16 h0, l0, h1, l1;
        split1(o[4 + p], h0, l0); split1(o[4 + p + 1], h1, l1);
        *(__nv_bfloat162*)(Hh + base + 128 + lane * 4 + p) = __nv_bfloat162(h0, h1);
        *(__nv_bfloat162*)(Hl + base + 128 + lane * 4 + p) = __nv_bfloat162(l0, l1);
    }
}

// ---------------- conv2 aggregation: batch rows, compact G2 via remap ----------------
__global__ void __launch_bounds__(256)
gcn_agg2_kernel(const float* __restrict__ G2, const float* __restrict__ bias,
                float* __restrict__ Out, int rows) {
    int v = (blockIdx.x * blockDim.x + threadIdx.x) >> 5;
    int lane = threadIdx.x & 31;
    if (v >= rows) return;
    float dv = g_dinv[v];

    const float4* Gv = (const float4*)(G2 + (size_t)g_remap[v] * DH);
    float4 acc0 = f4_fma(dv, Gv[lane],      make_float4(0.f, 0.f, 0.f, 0.f));
    float4 acc1 = f4_fma(dv, Gv[lane + 32], make_float4(0.f, 0.f, 0.f, 0.f));
    int s = g_rowptr[v], e = g_rowptr[v + 1];
    for (int j = s; j < e; j++) {
        int u = g_col[j];
        float w = g_dinv[u];
        const float4* Gu = (const float4*)(G2 + (size_t)g_remap[u] * DH);
        acc0 = f4_fma(w, Gu[lane],      acc0);
        acc1 = f4_fma(w, Gu[lane + 32], acc1);
    }
    const float4* b4 = (const float4*)bias;
    float4 bb0 = b4[lane], bb1 = b4[lane + 32];
    float4 o0, o1;
    o0.x = fmaf(dv, acc0.x, bb0.x); o0.y = fmaf(dv, acc0.y, bb0.y);
    o0.z = fmaf(dv, acc0.z, bb0.z); o0.w = fmaf(dv, acc0.w, bb0.w);
    o1.x = fmaf(dv, acc1.x, bb1.x); o1.y = fmaf(dv, acc1.y, bb1.y);
    o1.z = fmaf(dv, acc1.z, bb1.z); o1.w = fmaf(dv, acc1.w, bb1.w);
    float4* Ov = (float4*)(Out + (size_t)v * DH);
    Ov[lane] = o0; Ov[lane + 32] = o1;
}

// ---------------- tiny classifier ----------------
__global__ void classifier_kernel(const float* __restrict__ H3,
                                  const float* __restrict__ Wc,
                                  const float* __restrict__ bc,
                                  float* __restrict__ out, int rows) {
    int idx = blockIdx.x * blockDim.x + threadIdx.x;
    if (idx >= rows * 2) return;
    int r = idx >> 1, c = idx & 1;
    const float* h = H3 + (size_t)r * DOUT;
    float s = bc[c];
    #pragma unroll 8
    for (int k = 0; k < DOUT; k++) s = fmaf(h[k], Wc[k * 2 + c], s);
    out[idx] = s;
}

// ---------------- launch ----------------
extern "C" void kernel_launch(void* const* d_in, const int* in_sizes, int n_in,
                              void* d_out, int out_size) {
    const float* x    = (const float*)d_in[0];
    const void*  ei   = d_in[1];
    const float* W1   = (const float*)d_in[2];
    const float* b1   = (const float*)d_in[3];
    const float* Wg1  = (const float*)d_in[4];
    const float* bg1  = (const float*)d_in[5];
    const float* Wg2  = (const float*)d_in[6];
    const float* bg2  = (const float*)d_in[7];
    const float* W2   = (const float*)d_in[8];
    const float* b2   = (const float*)d_in[9];
    const float* Wc   = (const float*)d_in[10];
    const float* bc   = (const float*)d_in[11];

    int n = in_sizes[0] / DIN;
    int E = in_sizes[1] / 2;
    int batch = out_size / 2;
    if (n > N_MAX) n = N_MAX;
    if (E > E_MAX) E = E_MAX;
    if (batch > BATCH) batch = BATCH;

    float *G, *O2, *H3;
    int *deg, *need, *m2p;
    __nv_bfloat16 *xh, *xl, *H1h, *H1l, *H2h, *H2l, *Wth, *Wtl;
    cudaGetSymbolAddress((void**)&G,    g_G);
    cudaGetSymbolAddress((void**)&O2,   g_O2);
    cudaGetSymbolAddress((void**)&H3,   g_H3);
    cudaGetSymbolAddress((void**)&deg,  g_deg);
    cudaGetSymbolAddress((void**)&need, g_need);
    cudaGetSymbolAddress((void**)&m2p,  g_m2);
    cudaGetSymbolAddress((void**)&xh,   g_xh);
    cudaGetSymbolAddress((void**)&xl,   g_xl);
    cudaGetSymbolAddress((void**)&H1h,  g_H1h);
    cudaGetSymbolAddress((void**)&H1l,  g_H1l);
    cudaGetSymbolAddress((void**)&H2h,  g_H2h);
    cudaGetSymbolAddress((void**)&H2l,  g_H2l);
    cudaGetSymbolAddress((void**)&Wth,  g_Wth);
    cudaGetSymbolAddress((void**)&Wtl,  g_Wtl);

    static int smem_set = 0;
    if (!smem_set) {
        cudaFuncSetAttribute(tc_gemm_kernel,
                             cudaFuncAttributeMaxDynamicSharedMemorySize, TC_SMEM);
        smem_set = 1;
    }

    int nb = (n + 1023) / 1024;
    int mtiles = (n + 127) / 128;
    dim3 tcgrid(mtiles, 2);

    // ---- graph preprocessing + needed-set ----
    cudaMemsetAsync(deg, 0, (size_t)n * sizeof(int));
    cudaMemsetAsync(need, 0, (size_t)n * sizeof(int));
    sniff_kernel<<<1, 1>>>((const int*)ei);
    hist_kernel<<<(E + 255) / 256, 256>>>(ei, E, n);
    dinv_kernel<<<(n + 255) / 256, 256>>>(n);
    scan_part_kernel<<<nb, 1024>>>(n);
    scan_top_kernel<<<1, 32>>>(nb);
    scan_add_kernel<<<(n + 255) / 256, 256>>>(n, nb);
    fill_kernel<<<(E + 255) / 256, 256>>>(ei, E, n);
    mark_kernel<<<(E + 255) / 256, 256>>>(ei, E, n, batch);
    cscan_part_kernel<<<nb, 1024>>>(n);
    cscan_top_kernel<<<1, 32>>>(nb);
    cscan_add_kernel<<<(n + 255) / 256, 256>>>(n, nb);

    // ---- H1 = relu(x @ W1 + b1) -> bf16 hi/lo directly ----
    {
        size_t cnt = (size_t)n * DIN;
        split_kernel<<<(int)((cnt / 4 + 255) / 256), 256>>>(x, xh, xl, cnt);
        wtr_kernel<<<(DIN * 256 + 255) / 256, 256>>>(W1, Wth, Wtl, DIN);
        tc_gemm_kernel<<<tcgrid, 256, TC_SMEM>>>(xh, xl, Wth, Wtl, b1,
                                                 nullptr, H1h, H1l, n, nullptr, DIN, 1);
    }
    // ---- conv1: G = H1 @ Wg1 (fp32, full) ; H2 = agg(G) over S2 -> bf16 hi/lo compact ----
    {
        wtr_kernel<<<(DH * 256 + 255) / 256, 256>>>(Wg1, Wth, Wtl, DH);
        tc_gemm_kernel<<<tcgrid, 256, TC_SMEM>>>(H1h, H1l, Wth, Wtl, nullptr,
                                                 G, nullptr, nullptr, n, nullptr, DH, 0);
        gcn_agg_bf16_kernel<<<(n * 32 + 255) / 256, 256>>>(G, bg1, H2h, H2l);
    }
    // ---- conv2: G2 = H2c @ Wg2 (compact rows, M from device) ; O2 = agg2 ----
    {
        wtr_kernel<<<(DH * 256 + 255) / 256, 256>>>(Wg2, Wth, Wtl, DH);
        tc_gemm_kernel<<<tcgrid, 256, TC_SMEM>>>(H2h, H2l, Wth, Wtl, nullptr,
                                                 G, nullptr, nullptr, n, m2p, DH, 0);
        gcn_agg2_kernel<<<(batch * 32 + 255) / 256, 256>>>(G, bg2, O2, batch);
    }
    // ---- H3 = relu(O2 @ W2 + b2) ----
    {
        dim3 grid(DOUT / BN, (batch + BM - 1) / BM);
        sgemm_kernel<<<grid, 256>>>(O2, W2, b2, H3, batch, DOUT, DH, 1);
    }
    classifier_kernel<<<(batch * 2 + 255) / 256, 256>>>(H3, Wc, bc, (float*)d_out, batch);
}

// round 13
// speedup vs baseline: 2.2286x; 1.0452x over previous
#include <cuda_runtime.h>
#include <cuda_bf16.h>
#include <cstdint>

// ---------------- problem dims (fixed by dataset) ----------------
#define N_MAX   50000
#define E_MAX   800000
#define DIN     768
#define DH      256
#define DOUT    128
#define BATCH   1024

// ---------------- static scratch (no allocations allowed) ----------------
__device__ float g_G [(size_t)N_MAX * DH];   // GEMM2 out (full) / GEMM3 out (compact)
__device__ float g_O2[(size_t)BATCH * DH];
__device__ float g_H3[(size_t)BATCH * DOUT];
__device__ int   g_deg[N_MAX];
__device__ float g_dinv[N_MAX];
__device__ int   g_rowptr[N_MAX + 1];
__device__ int   g_cursor[N_MAX];
__device__ int   g_col[E_MAX];
__device__ int   g_is64;
__device__ int   g_bsum[64];
__device__ int   g_boff[66];
// pruning / compaction
__device__ int   g_need[N_MAX];
__device__ int   g_remap[N_MAX];
__device__ int   g_list2[N_MAX];
__device__ int   g_m2;
__device__ int   g_bsum2[64];
__device__ int   g_boff2[66];
// bf16-split operand buffers
__device__ __nv_bfloat16 g_H1h[(size_t)N_MAX * DH];
__device__ __nv_bfloat16 g_H1l[(size_t)N_MAX * DH];
__device__ __nv_bfloat16 g_H2h[(size_t)N_MAX * DH];   // compact rows
__device__ __nv_bfloat16 g_H2l[(size_t)N_MAX * DH];
__device__ __nv_bfloat16 g_W1th[(size_t)DH * DIN];    // W1^T  [256,768]
__device__ __nv_bfloat16 g_W1tl[(size_t)DH * DIN];
__device__ __nv_bfloat16 g_Wg1th[(size_t)DH * DH];    // Wg1^T [256,256]
__device__ __nv_bfloat16 g_Wg1tl[(size_t)DH * DH];
__device__ __nv_bfloat16 g_Wg2th[(size_t)DH * DH];    // Wg2^T [256,256]
__device__ __nv_bfloat16 g_Wg2tl[(size_t)DH * DH];

// ---------------- small helpers ----------------
__device__ __forceinline__ float4 f4_fma(float s, float4 a, float4 acc) {
    acc.x = fmaf(s, a.x, acc.x); acc.y = fmaf(s, a.y, acc.y);
    acc.z = fmaf(s, a.z, acc.z); acc.w = fmaf(s, a.w, acc.w);
    return acc;
}
__device__ __forceinline__ uint32_t smem_to_u32(const void* p) {
    uint32_t a;
    asm("{ .reg .u64 t; cvta.to.shared.u64 t, %1; cvt.u32.u64 %0, t; }" : "=r"(a) : "l"(p));
    return a;
}
__device__ __forceinline__ void cp_async16(uint32_t dst, const void* src) {
    asm volatile("cp.async.cg.shared.global [%0], [%1], 16;" :: "r"(dst), "l"(src));
}
__device__ __forceinline__ void cp_commit() { asm volatile("cp.async.commit_group;"); }
template <int N>
__device__ __forceinline__ void cp_wait() { asm volatile("cp.async.wait_group %0;" :: "n"(N)); }

__device__ __forceinline__ void ldm_x4(uint32_t* r, uint32_t addr) {
    asm volatile("ldmatrix.sync.aligned.m8n8.x4.shared.b16 {%0,%1,%2,%3}, [%4];"
                 : "=r"(r[0]), "=r"(r[1]), "=r"(r[2]), "=r"(r[3]) : "r"(addr));
}
__device__ __forceinline__ void mma_bf16(float* d, const uint32_t* a, const uint32_t* b) {
    asm volatile(
        "mma.sync.aligned.m16n8k16.row.col.f32.bf16.bf16.f32 "
        "{%0,%1,%2,%3}, {%4,%5,%6,%7}, {%8,%9}, {%0,%1,%2,%3};"
        : "+f"(d[0]), "+f"(d[1]), "+f"(d[2]), "+f"(d[3])
        : "r"(a[0]), "r"(a[1]), "r"(a[2]), "r"(a[3]), "r"(b[0]), "r"(b[1]));
}
__device__ __forceinline__ void split1(float a, __nv_bfloat16& h, __nv_bfloat16& l) {
    h = __float2bfloat16(a);
    l = __float2bfloat16(a - __bfloat162float(h));
}

// ---------------- dtype sniff ----------------
__global__ void sniff_kernel(const int* __restrict__ ei32) {
    int all0 = 1;
    for (int i = 0; i < 64; i++)
        if (ei32[2 * i + 1] != 0) { all0 = 0; break; }
    g_is64 = all0;
}
__device__ __forceinline__ int load_idx(const void* ei, size_t pos) {
    if (g_is64) return (int)((const long long*)ei)[pos];
    return ((const int*)ei)[pos];
}

// ---------------- graph preprocessing (merged hist + mark) ----------------
__global__ void histmark_kernel(const void* __restrict__ ei, int E, int n, int batch) {
    int e = blockIdx.x * blockDim.x + threadIdx.x;
    if (e < batch && e < n) g_need[e] = 1;            // self rows always needed
    if (e >= E) return;
    int d = load_idx(ei, (size_t)E + e);
    if ((unsigned)d < (unsigned)n) {
        atomicAdd(&g_deg[d], 1);
        if (d < batch) {
            int s = load_idx(ei, (size_t)e);
            if ((unsigned)s < (unsigned)n) g_need[s] = 1;
        }
    }
}

// dual scan: deg -> rowptr partials, need -> remap partials
__global__ void scan2_part_kernel(int n) {
    __shared__ int wsum[32];
    int t = threadIdx.x, b = blockIdx.x, i = b * 1024 + t;
    int lane = t & 31, w = t >> 5;
    // pass 1: deg
    {
        int v = (i < n) ? g_deg[i] : 0;
        int x = v;
        #pragma unroll
        for (int o = 1; o < 32; o <<= 1) { int y = __shfl_up_sync(0xffffffffu, x, o); if (lane >= o) x += y; }
        if (lane == 31) wsum[w] = x;
        __syncthreads();
        if (w == 0) {
            int s = wsum[lane];
            #pragma unroll
            for (int o = 1; o < 32; o <<= 1) { int y = __shfl_up_sync(0xffffffffu, s, o); if (lane >= o) s += y; }
            wsum[lane] = s;
        }
        __syncthreads();
        int off = w ? wsum[w - 1] : 0;
        int incl = x + off;
        if (i < n) g_rowptr[i] = incl - v;
        if (t == 1023) g_bsum[b] = incl;
    }
    __syncthreads();
    // pass 2: need
    {
        int v = (i < n) ? g_need[i] : 0;
        int x = v;
        #pragma unroll
        for (int o = 1; o < 32; o <<= 1) { int y = __shfl_up_sync(0xffffffffu, x, o); if (lane >= o) x += y; }
        if (lane == 31) wsum[w] = x;
        __syncthreads();
        if (w == 0) {
            int s = wsum[lane];
            #pragma unroll
            for (int o = 1; o < 32; o <<= 1) { int y = __shfl_up_sync(0xffffffffu, s, o); if (lane >= o) s += y; }
            wsum[lane] = s;
        }
        __syncthreads();
        int off = w ? wsum[w - 1] : 0;
        int incl = x + off;
        if (i < n) g_remap[i] = incl - v;
        if (t == 1023) g_bsum2[b] = incl;
    }
}
__global__ void scan2_top_kernel(int nb) {
    if (threadIdx.x == 0) {
        int acc = 0;
        for (int b = 0; b < nb; b++) { int s = g_bsum[b]; g_boff[b] = acc; acc += s; }
        g_boff[nb] = acc;
        acc = 0;
        for (int b = 0; b < nb; b++) { int s = g_bsum2[b]; g_boff2[b] = acc; acc += s; }
        g_boff2[nb] = acc;
    }
}
__global__ void scan2_add_kernel(int n, int nb) {
    int i = blockIdx.x * blockDim.x + threadIdx.x;
    if (i < n) {
        int val = g_rowptr[i] + g_boff[i >> 10];
        g_rowptr[i] = val; g_cursor[i] = val;
        int r = g_remap[i] + g_boff2[i >> 10];
        g_remap[i] = r;
        if (g_need[i]) g_list2[r] = i;
        g_dinv[i] = rsqrtf((float)(g_deg[i] + 1));
    }
    if (i == 0) { g_rowptr[n] = g_boff[nb]; g_m2 = g_boff2[nb]; }
}
__global__ void fill_kernel(const void* __restrict__ ei, int E, int n) {
    int e = blockIdx.x * blockDim.x + threadIdx.x;
    if (e >= E) return;
    int s = load_idx(ei, (size_t)e);
    int d = load_idx(ei, (size_t)E + e);
    if ((unsigned)d >= (unsigned)n || (unsigned)s >= (unsigned)n) return;
    int pos = atomicAdd(&g_cursor[d], 1);
    g_col[pos] = s;
}

// ---------------- W [K,256] fp32 -> W^T [256,K] bf16 hi/lo ----------------
__global__ void wtr_kernel(const float* __restrict__ W,
                           __nv_bfloat16* __restrict__ hi,
                           __nv_bfloat16* __restrict__ lo, int K) {
    int idx = blockIdx.x * blockDim.x + threadIdx.x;
    if (idx >= K * 256) return;
    int k = idx >> 8, nn = idx & 255;
    __nv_bfloat16 h, l; split1(W[idx], h, l);
    size_t o = (size_t)nn * K + k;
    hi[o] = h; lo[o] = l;
}

// ---------------- shared GEMM tile constants ----------------
#define ROW_B   80
#define TILE_B  (128 * ROW_B)
#define STAGE_B (4 * TILE_B)
#define TC_SMEM (2 * STAGE_B)

// ---------------- GEMM1: fp32 A with in-register bf16 hi/lo split ----------------
// C[M,256] = relu(A @ (Bh+Bl)^T + bias) -> bf16 hi/lo outputs
__global__ void __launch_bounds__(256)
tc_gemm1_kernel(const float* __restrict__ A,
                const __nv_bfloat16* __restrict__ Bh, const __nv_bfloat16* __restrict__ Bl,
                const float* __restrict__ bias,
                __nv_bfloat16* __restrict__ Ch, __nv_bfloat16* __restrict__ Cl,
                int M, int K) {
    extern __shared__ char smem[];
    const uint32_t sbase = smem_to_u32(smem);
    const int tid = threadIdx.x, lane = tid & 31, wid = tid >> 5;
    const int bm = blockIdx.x, bn = blockIdx.y;
    const int warpM = wid >> 1, warpN = wid & 1;

    const int lrow = tid >> 1, lseg = tid & 1;
    int arow = bm * 128 + lrow; if (arow >= M) arow = M - 1;
    const float* aP = A + (size_t)arow * K + lseg * 16;
    const __nv_bfloat16* bH0 = Bh + (size_t)(bn * 128 + lrow) * K + lseg * 16;
    const __nv_bfloat16* bL0 = Bl + (size_t)(bn * 128 + lrow) * K + lseg * 16;
    const uint32_t sdst = sbase + (uint32_t)lrow * ROW_B + (uint32_t)lseg * 32;
    char* sdstA = smem + (uint32_t)lrow * ROW_B + (uint32_t)lseg * 32;

    const int nk = K >> 5;
    float areg[16];

    auto ldgA = [&](int c) {
        const float4* p = (const float4*)(aP + (c << 5));
        *(float4*)(areg + 0)  = p[0];
        *(float4*)(areg + 4)  = p[1];
        *(float4*)(areg + 8)  = p[2];
        *(float4*)(areg + 12) = p[3];
    };
    auto stsA = [&](int c) {
        char* p = sdstA + (uint32_t)(c & 1) * STAGE_B;
        __nv_bfloat162 hh[8], ll[8];
        #pragma unroll
        for (int j = 0; j < 8; j++) {
            __nv_bfloat16 h0, l0, h1, l1;
            split1(areg[2 * j], h0, l0); split1(areg[2 * j + 1], h1, l1);
            hh[j] = __nv_bfloat162(h0, h1); ll[j] = __nv_bfloat162(l0, l1);
        }
        ((uint4*)p)[0]               = ((uint4*)hh)[0];
        ((uint4*)(p + 16))[0]        = ((uint4*)hh)[1];
        ((uint4*)(p + TILE_B))[0]    = ((uint4*)ll)[0];
        ((uint4*)(p + TILE_B + 16))[0] = ((uint4*)ll)[1];
    };
    auto issueB = [&](int c) {
        uint32_t so = (uint32_t)(c & 1) * STAGE_B;
        int k0 = c << 5;
        cp_async16(sdst + so + 2 * TILE_B,      bH0 + k0);
        cp_async16(sdst + so + 2 * TILE_B + 16, bH0 + k0 + 8);
        cp_async16(sdst + so + 3 * TILE_B,      bL0 + k0);
        cp_async16(sdst + so + 3 * TILE_B + 16, bL0 + k0 + 8);
        cp_commit();
    };

    float acc[2][8][4];
    #pragma unroll
    for (int mi = 0; mi < 2; mi++)
        #pragma unroll
        for (int ni = 0; ni < 8; ni++)
            #pragma unroll
            for (int r = 0; r < 4; r++) acc[mi][ni][r] = 0.f;

    ldgA(0); issueB(0);

    const uint32_t a_off = (uint32_t)(warpM * 32 + (lane & 15)) * ROW_B + ((lane >> 4) << 4);
    const uint32_t b_off = (uint32_t)(warpN * 64 + ((lane >> 4) << 3) + (lane & 7)) * ROW_B
                         + (((lane >> 3) & 1) << 4);

    for (int c = 0; c < nk; c++) {
        stsA(c);
        if (c + 1 < nk) { ldgA(c + 1); issueB(c + 1); cp_wait<1>(); }
        else            { cp_wait<0>(); }
        __syncthreads();

        const uint32_t so = sbase + (uint32_t)(c & 1) * STAGE_B;
        #pragma unroll
        for (int ks = 0; ks < 2; ks++) {
            uint32_t a_h[2][4], a_l[2][4];
            #pragma unroll
            for (int mi = 0; mi < 2; mi++) {
                uint32_t off = a_off + (uint32_t)mi * 16 * ROW_B + ks * 32;
                ldm_x4(a_h[mi], so + off);
                ldm_x4(a_l[mi], so + TILE_B + off);
            }
            uint32_t b_h[8][2], b_l[8][2];
            #pragma unroll
            for (int np = 0; np < 4; np++) {
                uint32_t off = b_off + (uint32_t)np * 16 * ROW_B + ks * 32;
                uint32_t t[4];
                ldm_x4(t, so + 2 * TILE_B + off);
                b_h[np * 2][0] = t[0]; b_h[np * 2][1] = t[1];
                b_h[np * 2 + 1][0] = t[2]; b_h[np * 2 + 1][1] = t[3];
                ldm_x4(t, so + 3 * TILE_B + off);
                b_l[np * 2][0] = t[0]; b_l[np * 2][1] = t[1];
                b_l[np * 2 + 1][0] = t[2]; b_l[np * 2 + 1][1] = t[3];
            }
            #pragma unroll
            for (int mi = 0; mi < 2; mi++)
                #pragma unroll
                for (int ni = 0; ni < 8; ni++) {
                    mma_bf16(acc[mi][ni], a_h[mi], b_h[ni]);
                    mma_bf16(acc[mi][ni], a_h[mi], b_l[ni]);
                    mma_bf16(acc[mi][ni], a_l[mi], b_h[ni]);
                }
        }
        __syncthreads();
    }

    const int r0 = bm * 128 + warpM * 32 + (lane >> 2);
    const int c0 = bn * 128 + warpN * 64 + (lane & 3) * 2;
    #pragma unroll
    for (int mi = 0; mi < 2; mi++) {
        #pragma unroll
        for (int ni = 0; ni < 8; ni++) {
            int col = c0 + ni * 8;
            float bx = bias[col], by = bias[col + 1];
            #pragma unroll
            for (int half = 0; half < 2; half++) {
                int row = r0 + mi * 16 + half * 8;
                if (row < M) {
                    float vx = fmaxf(acc[mi][ni][half * 2 + 0] + bx, 0.f);
                    float vy = fmaxf(acc[mi][ni][half * 2 + 1] + by, 0.f);
                    __nv_bfloat16 hx, lx, hy, ly;
                    split1(vx, hx, lx); split1(vy, hy, ly);
                    *(__nv_bfloat162*)(Ch + (size_t)row * 256 + col) = __nv_bfloat162(hx, hy);
                    *(__nv_bfloat162*)(Cl + (size_t)row * 256 + col) = __nv_bfloat162(lx, ly);
                }
            }
        }
    }
}

// ---------------- GEMM2/3: bf16-split A (pre-split), fp32 out ----------------
__global__ void __launch_bounds__(256)
tc_gemm_kernel(const __nv_bfloat16* __restrict__ Ah, const __nv_bfloat16* __restrict__ Al,
               const __nv_bfloat16* __restrict__ Bh, const __nv_bfloat16* __restrict__ Bl,
               float* __restrict__ C,
               int M, const int* __restrict__ Mdev, int K) {
    if (Mdev) M = *Mdev;
    const int bm = blockIdx.x, bn = blockIdx.y;
    if (bm * 128 >= M) return;

    extern __shared__ char smem[];
    const uint32_t sbase = smem_to_u32(smem);
    const int tid = threadIdx.x, lane = tid & 31, wid = tid >> 5;
    const int warpM = wid >> 1, warpN = wid & 1;

    const int lrow = tid >> 1, lseg = tid & 1;
    int arow = bm * 128 + lrow; if (arow >= M) arow = M - 1;
    const __nv_bfloat16* aH = Ah + (size_t)arow * K + lseg * 16;
    const __nv_bfloat16* aL = Al + (size_t)arow * K + lseg * 16;
    const __nv_bfloat16* bH = Bh + (size_t)(bn * 128 + lrow) * K + lseg * 16;
    const __nv_bfloat16* bL = Bl + (size_t)(bn * 128 + lrow) * K + lseg * 16;
    const uint32_t sdst = sbase + (uint32_t)lrow * ROW_B + (uint32_t)lseg * 32;

    const int nk = K >> 5;

    auto issue_stage = [&](int c) {
        const uint32_t so = (uint32_t)(c & 1) * STAGE_B;
        const int k0 = c << 5;
        cp_async16(sdst + so,                 aH + k0);
        cp_async16(sdst + so + 16,            aH + k0 + 8);
        cp_async16(sdst + so + TILE_B,        aL + k0);
        cp_async16(sdst + so + TILE_B + 16,   aL + k0 + 8);
        cp_async16(sdst + so + 2 * TILE_B,      bH + k0);
        cp_async16(sdst + so + 2 * TILE_B + 16, bH + k0 + 8);
        cp_async16(sdst + so + 3 * TILE_B,      bL + k0);
        cp_async16(sdst + so + 3 * TILE_B + 16, bL + k0 + 8);
        cp_commit();
    };

    float acc[2][8][4];
    #pragma unroll
    for (int mi = 0; mi < 2; mi++)
        #pragma unroll
        for (int ni = 0; ni < 8; ni++)
            #pragma unroll
            for (int r = 0; r < 4; r++) acc[mi][ni][r] = 0.f;

    issue_stage(0);

    const uint32_t a_off = (uint32_t)(warpM * 32 + (lane & 15)) * ROW_B + ((lane >> 4) << 4);
    const uint32_t b_off = (uint32_t)(warpN * 64 + ((lane >> 4) << 3) + (lane & 7)) * ROW_B
                         + (((lane >> 3) & 1) << 4);

    for (int c = 0; c < nk; c++) {
        if (c + 1 < nk) { issue_stage(c + 1); cp_wait<1>(); }
        else            { cp_wait<0>(); }
        __syncthreads();

        const uint32_t so = sbase + (uint32_t)(c & 1) * STAGE_B;
        #pragma unroll
        for (int ks = 0; ks < 2; ks++) {
            uint32_t a_h[2][4], a_l[2][4];
            #pragma unroll
            for (int mi = 0; mi < 2; mi++) {
                uint32_t off = a_off + (uint32_t)mi * 16 * ROW_B + ks * 32;
                ldm_x4(a_h[mi], so + off);
                ldm_x4(a_l[mi], so + TILE_B + off);
            }
            uint32_t b_h[8][2], b_l[8][2];
            #pragma unroll
            for (int np = 0; np < 4; np++) {
                uint32_t off = b_off + (uint32_t)np * 16 * ROW_B + ks * 32;
                uint32_t t[4];
                ldm_x4(t, so + 2 * TILE_B + off);
                b_h[np * 2][0] = t[0]; b_h[np * 2][1] = t[1];
                b_h[np * 2 + 1][0] = t[2]; b_h[np * 2 + 1][1] = t[3];
                ldm_x4(t, so + 3 * TILE_B + off);
                b_l[np * 2][0] = t[0]; b_l[np * 2][1] = t[1];
                b_l[np * 2 + 1][0] = t[2]; b_l[np * 2 + 1][1] = t[3];
            }
            #pragma unroll
            for (int mi = 0; mi < 2; mi++)
                #pragma unroll
                for (int ni = 0; ni < 8; ni++) {
                    mma_bf16(acc[mi][ni], a_h[mi], b_h[ni]);
                    mma_bf16(acc[mi][ni], a_h[mi], b_l[ni]);
                    mma_bf16(acc[mi][ni], a_l[mi], b_h[ni]);
                }
        }
        __syncthreads();
    }

    const int r0 = bm * 128 + warpM * 32 + (lane >> 2);
    const int c0 = bn * 128 + warpN * 64 + (lane & 3) * 2;
    #pragma unroll
    for (int mi = 0; mi < 2; mi++) {
        #pragma unroll
        for (int ni = 0; ni < 8; ni++) {
            int col = c0 + ni * 8;
            #pragma unroll
            for (int half = 0; half < 2; half++) {
                int row = r0 + mi * 16 + half * 8;
                if (row < M) {
                    *(float2*)(C + (size_t)row * 256 + col) =
                        make_float2(acc[mi][ni][half * 2 + 0], acc[mi][ni][half * 2 + 1]);
                }
            }
        }
    }
}

// ---------------- fp32 tiled GEMM (tiny 1024-row linear) ----------------
#define BM 128
#define BN 128
#define BK 8
#define TM 8
#define TN 8
__global__ void __launch_bounds__(256)
sgemm_kernel(const float* __restrict__ A, const float* __restrict__ B,
             const float* __restrict__ bias, float* __restrict__ C,
             int M, int N, int K, int doRelu) {
    __shared__ float As[BK][BM];
    __shared__ float Bs[BK][BN];
    int tid = threadIdx.x;
    int bm = blockIdx.y, bn = blockIdx.x;
    int tx = tid & 15, ty = tid >> 4;
    float acc[TM][TN];
    #pragma unroll
    for (int i = 0; i < TM; i++)
        #pragma unroll
        for (int j = 0; j < TN; j++) acc[i][j] = 0.f;
    int rowA = tid >> 1, colA = (tid & 1) * 4;
    int rowB = tid >> 5, colB = (tid & 31) * 4;
    int gRowA = bm * BM + rowA;
    bool aValid = gRowA < M;
    const float* Aptr = A + (size_t)(aValid ? gRowA : 0) * K + colA;
    const float* Bptr = B + (size_t)rowB * N + bn * BN + colB;
    for (int k0 = 0; k0 < K; k0 += BK) {
        float4 a4 = aValid ? *(const float4*)Aptr : make_float4(0.f, 0.f, 0.f, 0.f);
        float4 b4 = *(const float4*)Bptr;
        As[colA + 0][rowA] = a4.x; As[colA + 1][rowA] = a4.y;
        As[colA + 2][rowA] = a4.z; As[colA + 3][rowA] = a4.w;
        *(float4*)&Bs[rowB][colB] = b4;
        __syncthreads();
        #pragma unroll
        for (int k = 0; k < BK; k++) {
            float ra[TM], rb[TN];
            #pragma unroll
            for (int i = 0; i < TM; i += 4) *(float4*)&ra[i] = *(const float4*)&As[k][ty * TM + i];
            #pragma unroll
            for (int j = 0; j < TN; j += 4) *(float4*)&rb[j] = *(const float4*)&Bs[k][tx * TN + j];
            #pragma unroll
            for (int i = 0; i < TM; i++)
                #pragma unroll
                for (int j = 0; j < TN; j++)
                    acc[i][j] = fmaf(ra[i], rb[j], acc[i][j]);
        }
        __syncthreads();
        Aptr += BK; Bptr += (size_t)BK * N;
    }
    int crow0 = bm * BM + ty * TM, ccol0 = bn * BN + tx * TN;
    float bvals[TN];
    #pragma unroll
    for (int j = 0; j < TN; j++) bvals[j] = bias ? bias[ccol0 + j] : 0.f;
    #pragma unroll
    for (int i = 0; i < TM; i++) {
        int r = crow0 + i;
        if (r >= M) break;
        float* cptr = C + (size_t)r * N + ccol0;
        #pragma unroll
        for (int j = 0; j < TN; j += 4) {
            float4 v;
            v.x = acc[i][j + 0] + bvals[j + 0]; v.y = acc[i][j + 1] + bvals[j + 1];
            v.z = acc[i][j + 2] + bvals[j + 2]; v.w = acc[i][j + 3] + bvals[j + 3];
            if (doRelu) {
                v.x = fmaxf(v.x, 0.f); v.y = fmaxf(v.y, 0.f);
                v.z = fmaxf(v.z, 0.f); v.w = fmaxf(v.w, 0.f);
            }
            *(float4*)(cptr + j) = v;
        }
    }
}

// ---------------- conv1 aggregation over compact list, bf16 hi/lo output ----------------
__global__ void __launch_bounds__(256)
gcn_agg_bf16_kernel(const float* __restrict__ G, const float* __restrict__ bias,
                    __nv_bfloat16* __restrict__ Hh, __nv_bfloat16* __restrict__ Hl) {
    int i = (blockIdx.x * blockDim.x + threadIdx.x) >> 5;
    int lane = threadIdx.x & 31;
    if (i >= g_m2) return;
    int v = g_list2[i];
    float dv = g_dinv[v];

    const float4* Gv = (const float4*)(G + (size_t)v * DH);
    float4 acc0 = f4_fma(dv, Gv[lane],      make_float4(0.f, 0.f, 0.f, 0.f));
    float4 acc1 = f4_fma(dv, Gv[lane + 32], make_float4(0.f, 0.f, 0.f, 0.f));
    int s = g_rowptr[v], e = g_rowptr[v + 1];
    for (int j = s; j < e; j++) {
        int u = g_col[j];
        float w = g_dinv[u];
        const float4* Gu = (const float4*)(G + (size_t)u * DH);
        acc0 = f4_fma(w, Gu[lane],      acc0);
        acc1 = f4_fma(w, Gu[lane + 32], acc1);
    }
    const float4* b4 = (const float4*)bias;
    float4 bb0 = b4[lane], bb1 = b4[lane + 32];
    float o[8];
    o[0] = fmaf(dv, acc0.x, bb0.x); o[1] = fmaf(dv, acc0.y, bb0.y);
    o[2] = fmaf(dv, acc0.z, bb0.z); o[3] = fmaf(dv, acc0.w, bb0.w);
    o[4] = fmaf(dv, acc1.x, bb1.x); o[5] = fmaf(dv, acc1.y, bb1.y);
    o[6] = fmaf(dv, acc1.z, bb1.z); o[7] = fmaf(dv, acc1.w, bb1.w);

    size_t base = (size_t)i * DH;
    #pragma unroll
    for (int p = 0; p < 4; p += 2) {
        __nv_bfloat16 h0, l0, h1, l1;
        split1(o[p], h0, l0); split1(o[p + 1], h1, l1);
        *(__nv_bfloat162*)(Hh + base + lane * 4 + p) = __nv_bfloat162(h0, h1);
        *(__nv_bfloat162*)(Hl + base + lane * 4 + p) = __nv_bfloat162(l0, l1);
    }
    #pragma unroll
    for (int p = 0; p < 4; p += 2) {
        __nv_bfloat16 h0, l0, h1, l1;
        split1(o[4 + p], h0, l0); split1(o[4 + p + 1], h1, l1);
        *(__nv_bfloat162*)(Hh + base + 128 + lane * 4 + p) = __nv_bfloat162(h0, h1);
        *(__nv_bfloat162*)(Hl + base + 128 + lane * 4 + p) = __nv_bfloat162(l0, l1);
    }
}

// ---------------- conv2 aggregation: batch rows, compact G2 via remap ----------------
__global__ void __launch_bounds__(256)
gcn_agg2_kernel(const float* __restrict__ G2, const float* __restrict__ bias,
                float* __restrict__ Out, int rows) {
    int v = (blockIdx.x * blockDim.x + threadIdx.x) >> 5;
    int lane = threadIdx.x & 31;
    if (v >= rows) return;
    float dv = g_dinv[v];

    const float4* Gv = (const float4*)(G2 + (size_t)g_remap[v] * DH);
    float4 acc0 = f4_fma(dv, Gv[lane],      make_float4(0.f, 0.f, 0.f, 0.f));
    float4 acc1 = f4_fma(dv, Gv[lane + 32], make_float4(0.f, 0.f, 0.f, 0.f));
    int s = g_rowptr[v], e = g_rowptr[v + 1];
    for (int j = s; j < e; j++) {
        int u = g_col[j];
        float w = g_dinv[u];
        const float4* Gu = (const float4*)(G2 + (size_t)g_remap[u] * DH);
        acc0 = f4_fma(w, Gu[lane],      acc0);
        acc1 = f4_fma(w, Gu[lane + 32], acc1);
    }
    const float4* b4 = (const float4*)bias;
    float4 bb0 = b4[lane], bb1 = b4[lane + 32];
    float4 o0, o1;
    o0.x = fmaf(dv, acc0.x, bb0.x); o0.y = fmaf(dv, acc0.y, bb0.y);
    o0.z = fmaf(dv, acc0.z, bb0.z); o0.w = fmaf(dv, acc0.w, bb0.w);
    o1.x = fmaf(dv, acc1.x, bb1.x); o1.y = fmaf(dv, acc1.y, bb1.y);
    o1.z = fmaf(dv, acc1.z, bb1.z); o1.w = fmaf(dv, acc1.w, bb1.w);
    float4* Ov = (float4*)(Out + (size_t)v * DH);
    Ov[lane] = o0; Ov[lane + 32] = o1;
}

// ---------------- tiny classifier ----------------
__global__ void classifier_kernel(const float* __restrict__ H3,
                                  const float* __restrict__ Wc,
                                  const float* __restrict__ bc,
                                  float* __restrict__ out, int rows) {
    int idx = blockIdx.x * blockDim.x + threadIdx.x;
    if (idx >= rows * 2) return;
    int r = idx >> 1, c = idx & 1;
    const float* h = H3 + (size_t)r * DOUT;
    float s = bc[c];
    #pragma unroll 8
    for (int k = 0; k < DOUT; k++) s = fmaf(h[k], Wc[k * 2 + c], s);
    out[idx] = s;
}

// ---------------- launch ----------------
extern "C" void kernel_launch(void* const* d_in, const int* in_sizes, int n_in,
                              void* d_out, int out_size) {
    const float* x    = (const float*)d_in[0];
    const void*  ei   = d_in[1];
    const float* W1   = (const float*)d_in[2];
    const float* b1   = (const float*)d_in[3];
    const float* Wg1  = (const float*)d_in[4];
    const float* bg1  = (const float*)d_in[5];
    const float* Wg2  = (const float*)d_in[6];
    const float* bg2  = (const float*)d_in[7];
    const float* W2   = (const float*)d_in[8];
    const float* b2   = (const float*)d_in[9];
    const float* Wc   = (const float*)d_in[10];
    const float* bc   = (const float*)d_in[11];

    int n = in_sizes[0] / DIN;
    int E = in_sizes[1] / 2;
    int batch = out_size / 2;
    if (n > N_MAX) n = N_MAX;
    if (E > E_MAX) E = E_MAX;
    if (batch > BATCH) batch = BATCH;

    float *G, *O2, *H3;
    int *deg, *need, *m2p;
    __nv_bfloat16 *H1h, *H1l, *H2h, *H2l;
    __nv_bfloat16 *W1th, *W1tl, *Wg1th, *Wg1tl, *Wg2th, *Wg2tl;
    cudaGetSymbolAddress((void**)&G,     g_G);
    cudaGetSymbolAddress((void**)&O2,    g_O2);
    cudaGetSymbolAddress((void**)&H3,    g_H3);
    cudaGetSymbolAddress((void**)&deg,   g_deg);
    cudaGetSymbolAddress((void**)&need,  g_need);
    cudaGetSymbolAddress((void**)&m2p,   g_m2);
    cudaGetSymbolAddress((void**)&H1h,   g_H1h);
    cudaGetSymbolAddress((void**)&H1l,   g_H1l);
    cudaGetSymbolAddress((void**)&H2h,   g_H2h);
    cudaGetSymbolAddress((void**)&H2l,   g_H2l);
    cudaGetSymbolAddress((void**)&W1th,  g_W1th);
    cudaGetSymbolAddress((void**)&W1tl,  g_W1tl);
    cudaGetSymbolAddress((void**)&Wg1th, g_Wg1th);
    cudaGetSymbolAddress((void**)&Wg1tl, g_Wg1tl);
    cudaGetSymbolAddress((void**)&Wg2th, g_Wg2th);
    cudaGetSymbolAddress((void**)&Wg2tl, g_Wg2tl);

    static int smem_set = 0;
    if (!smem_set) {
        cudaFuncSetAttribute(tc_gemm_kernel,
                             cudaFuncAttributeMaxDynamicSharedMemorySize, TC_SMEM);
        cudaFuncSetAttribute(tc_gemm1_kernel,
                             cudaFuncAttributeMaxDynamicSharedMemorySize, TC_SMEM);
        smem_set = 1;
    }

    int nb = (n + 1023) / 1024;
    int mtiles = (n + 127) / 128;
    dim3 tcgrid(mtiles, 2);

    // ---- weight transposes first (separate buffers), then big GEMMs ----
    wtr_kernel<<<(DIN * 256 + 255) / 256, 256>>>(W1,  W1th,  W1tl,  DIN);
    wtr_kernel<<<(DH * 256 + 255) / 256, 256>>>(Wg1, Wg1th, Wg1tl, DH);
    wtr_kernel<<<(DH * 256 + 255) / 256, 256>>>(Wg2, Wg2th, Wg2tl, DH);

    // GEMM1: H1 = relu(x @ W1 + b1) -> bf16 hi/lo (fp32 A, in-kernel split)
    tc_gemm1_kernel<<<tcgrid, 256, TC_SMEM>>>(x, W1th, W1tl, b1, H1h, H1l, n, DIN);
    // GEMM2: G = H1 @ Wg1 (fp32 out, full rows)
    tc_gemm_kernel<<<tcgrid, 256, TC_SMEM>>>(H1h, H1l, Wg1th, Wg1tl, G, n, nullptr, DH);

    // ---- graph preprocessing + needed-set (overlaps nothing; stream-serial after GEMMs) ----
    cudaMemsetAsync(deg, 0, (size_t)n * sizeof(int));
    cudaMemsetAsync(need, 0, (size_t)n * sizeof(int));
    sniff_kernel<<<1, 1>>>((const int*)ei);
    histmark_kernel<<<(E + 255) / 256, 256>>>(ei, E, n, batch);
    scan2_part_kernel<<<nb, 1024>>>(n);
    scan2_top_kernel<<<1, 32>>>(nb);
    scan2_add_kernel<<<(n + 255) / 256, 256>>>(n, nb);
    fill_kernel<<<(E + 255) / 256, 256>>>(ei, E, n);

    // conv1 aggregation over compact list -> H2 bf16 hi/lo
    gcn_agg_bf16_kernel<<<(n * 32 + 255) / 256, 256>>>(G, bg1, H2h, H2l);
    // GEMM3: G2 = H2c @ Wg2 (compact rows, M from device)
    tc_gemm_kernel<<<tcgrid, 256, TC_SMEM>>>(H2h, H2l, Wg2th, Wg2tl, G, n, m2p, DH);
    // conv2 aggregation -> O2
    gcn_agg2_kernel<<<(batch * 32 + 255) / 256, 256>>>(G, bg2, O2, batch);
    // H3 = relu(O2 @ W2 + b2)
    {
        dim3 grid(DOUT / BN, (batch + BM - 1) / BM);
        sgemm_kernel<<<grid, 256>>>(O2, W2, b2, H3, batch, DOUT, DH, 1);
    }
    classifier_kernel<<<(batch * 2 + 255) / 256, 256>>>(H3, Wc, bc, (float*)d_out, batch);
}